// round 4
// baseline (speedup 1.0000x reference)
#include <cuda_runtime.h>
#include <math.h>

// Problem dims (fixed)
#define BDIM 2
#define TDIM 2048
#define CDIM 1024
#define NH   16
#define HD   64
#define MROWS (BDIM*TDIM)   // 4096

// ---------------- device scratch (no allocations allowed) ----------------
__device__ float g_q[(size_t)MROWS*CDIM];   // 16 MB  q after rope, (B,T,H,HD) packed as (M,C)
__device__ float g_k[(size_t)MROWS*HD];     // 1 MB   k after rope
__device__ float g_v[(size_t)MROWS*HD];
__device__ float g_att[(size_t)MROWS*CDIM]; // attention output pre-Wo

// =========================================================================
// Generic tiled SGEMM:  C[M,N] = A[M,K] @ B[K,N] + bias[N]
// Requires M%BM==0, N%BN==0, K%BK==0 (true for all our shapes).
// =========================================================================
template<int BM,int BN,int BK,int TM,int TN>
__global__ void __launch_bounds__((BM/TM)*(BN/TN))
sgemm_bias_kernel(const float* __restrict__ A, const float* __restrict__ B,
                  const float* __restrict__ bias, float* __restrict__ C,
                  int M, int N, int K)
{
    constexpr int THREADS = (BM/TM)*(BN/TN);
    __shared__ float As[BK][BM];
    __shared__ float Bs[BK][BN];

    const int tid  = threadIdx.x;
    const int tcol = tid % (BN/TN);
    const int trow = tid / (BN/TN);
    const int rowBase = blockIdx.y * BM;
    const int colBase = blockIdx.x * BN;

    float acc[TM][TN];
#pragma unroll
    for (int i = 0; i < TM; i++)
#pragma unroll
        for (int j = 0; j < TN; j++) acc[i][j] = 0.0f;

    constexpr int A_LOADS = (BM*BK)/(4*THREADS);
    constexpr int B_LOADS = (BK*BN)/(4*THREADS);
    static_assert(A_LOADS >= 1 && B_LOADS >= 1, "tile/threads mismatch");

    for (int k0 = 0; k0 < K; k0 += BK) {
#pragma unroll
        for (int i = 0; i < A_LOADS; i++) {
            int idx = tid + i*THREADS;               // one float4 per idx
            int r  = idx / (BK/4);
            int c4 = (idx % (BK/4))*4;
            float4 v = *(const float4*)&A[(size_t)(rowBase + r)*K + k0 + c4];
            As[c4+0][r] = v.x; As[c4+1][r] = v.y;
            As[c4+2][r] = v.z; As[c4+3][r] = v.w;
        }
#pragma unroll
        for (int i = 0; i < B_LOADS; i++) {
            int idx = tid + i*THREADS;
            int r  = idx / (BN/4);
            int c4 = (idx % (BN/4))*4;
            *(float4*)&Bs[r][c4] = *(const float4*)&B[(size_t)(k0 + r)*N + colBase + c4];
        }
        __syncthreads();

#pragma unroll
        for (int k = 0; k < BK; k++) {
            float rm[TM], rn[TN];
#pragma unroll
            for (int i = 0; i < TM; i += 4) {
                float4 t4 = *(const float4*)&As[k][trow*TM + i];
                rm[i]=t4.x; rm[i+1]=t4.y; rm[i+2]=t4.z; rm[i+3]=t4.w;
            }
#pragma unroll
            for (int j = 0; j < TN; j += 4) {
                float4 t4 = *(const float4*)&Bs[k][tcol*TN + j];
                rn[j]=t4.x; rn[j+1]=t4.y; rn[j+2]=t4.z; rn[j+3]=t4.w;
            }
#pragma unroll
            for (int i = 0; i < TM; i++)
#pragma unroll
                for (int j = 0; j < TN; j++)
                    acc[i][j] += rm[i]*rn[j];
        }
        __syncthreads();
    }

#pragma unroll
    for (int i = 0; i < TM; i++) {
        int r = rowBase + trow*TM + i;
#pragma unroll
        for (int j = 0; j < TN; j += 4) {
            int c = colBase + tcol*TN + j;
            float4 v;
            v.x = acc[i][j+0] + bias[c+0];
            v.y = acc[i][j+1] + bias[c+1];
            v.z = acc[i][j+2] + bias[c+2];
            v.w = acc[i][j+3] + bias[c+3];
            *(float4*)&C[(size_t)r*N + c] = v;
        }
    }
}

// =========================================================================
// RoPE: in-place on q (B,T,H,HD) and k (B,T,1,HD).
// out[d]    = t1*cos + t2*sin   (d < 32)
// out[d+32] = t1*sin - t2*cos
// =========================================================================
__global__ void rope_kernel(float* __restrict__ q, float* __restrict__ k)
{
    const int total = BDIM*TDIM*(NH+1)*(HD/2);
    int idx = blockIdx.x*blockDim.x + threadIdx.x;
    if (idx >= total) return;
    int pr   = idx & 31;            // pair index 0..31
    int rest = idx >> 5;
    int hh   = rest % (NH+1);       // 0..15 -> q head, 16 -> k
    int bt   = rest / (NH+1);       // 0..4095
    int t    = bt & (TDIM-1);

    // inv_freq = 10000^(-pr/32)
    float inv_freq = expf(-(float)pr * (9.2103403719761836f / 32.0f));
    float ang = (float)t * inv_freq;
    float sn, cs;
    sincosf(ang, &sn, &cs);         // accurate version: args up to ~2047 rad

    float* base = (hh < NH) ? (q + (size_t)bt*CDIM + hh*HD)
                            : (k + (size_t)bt*HD);
    float t1 = base[pr];
    float t2 = base[pr + 32];
    base[pr]      = t1*cs + t2*sn;
    base[pr + 32] = t1*sn - t2*cs;
}

// =========================================================================
// Causal MQA flash attention. BQ=BKV=64, HD=64, 256 threads.
// Thread map: tc = tid&15 -> 4 columns (kv for S, head-dim for O),
//             tr = tid>>4 -> 4 rows (query rows). Row groups = half warps,
//             so softmax reductions use 16-lane shuffles + __syncwarp only.
// =========================================================================
#define QSS 68   // Qs row stride (pad: breaks broadcast bank collision)
#define KTS 68   // Kt row stride
#define VSS 64
#define PSS 68
#define ATT_SMEM_FLOATS (64*QSS + 64*KTS + 64*VSS + 64*PSS)
#define ATT_SMEM_BYTES  (ATT_SMEM_FLOATS*4)

__global__ void __launch_bounds__(256)
attn_kernel(const float* __restrict__ gq, const float* __restrict__ gk,
            const float* __restrict__ gv, float* __restrict__ go)
{
    extern __shared__ float sm[];
    float* Qs = sm;                  // [64][QSS]  Qs[r][d] (pre-scaled by 1/8)
    float* Kt = Qs + 64*QSS;         // [64][KTS]  Kt[d][c]  (K transposed)
    float* Vs = Kt + 64*KTS;         // [64][VSS]  Vs[c][d]
    float* Ps = Vs + 64*VSS;         // [64][PSS]  Ps[r][c]

    const int qtile = blockIdx.x;
    const int h     = blockIdx.y;
    const int b     = blockIdx.z;
    const int tid   = threadIdx.x;
    const int tc    = tid & 15;
    const int tr    = tid >> 4;
    const int r0    = tr*4, c0 = tc*4;
    const int qbase = qtile*64;

    // ---- load Q tile (scaled by 1/sqrt(HD) = 0.125) ----
    {
        const float* qp = gq + ((size_t)(b*TDIM + qbase))*CDIM + h*HD;
#pragma unroll
        for (int i = 0; i < 4; i++) {
            int idx = tid + i*256;
            int r = idx >> 4, d4 = (idx & 15) << 2;
            float4 v = *(const float4*)(qp + (size_t)r*CDIM + d4);
            Qs[r*QSS + d4+0] = v.x*0.125f;
            Qs[r*QSS + d4+1] = v.y*0.125f;
            Qs[r*QSS + d4+2] = v.z*0.125f;
            Qs[r*QSS + d4+3] = v.w*0.125f;
        }
    }

    float o[4][4];
    float m_[4], l_[4];
#pragma unroll
    for (int i = 0; i < 4; i++) {
        m_[i] = -1e30f; l_[i] = 0.0f;
#pragma unroll
        for (int j = 0; j < 4; j++) o[i][j] = 0.0f;
    }

    const int ntiles = qtile + 1;     // causal: only tiles <= diagonal
    for (int t = 0; t < ntiles; t++) {
        const int kvbase = t*64;
        __syncthreads();   // previous iteration done with Kt/Vs

        // K tile, transposed store Kt[d][c] (coalesced scalar loads)
        {
            const float* kp = gk + ((size_t)(b*TDIM + kvbase))*HD;
#pragma unroll
            for (int i = 0; i < 16; i++) {
                int idx = tid + i*256;      // 4096 elems
                int d = idx & 63, rk = idx >> 6;
                Kt[d*KTS + rk] = kp[rk*HD + d];
            }
            const float* vp = gv + ((size_t)(b*TDIM + kvbase))*HD;
#pragma unroll
            for (int i = 0; i < 4; i++) {
                int idx = tid + i*256;
                int r = idx >> 4, d4 = (idx & 15) << 2;
                *(float4*)(Vs + r*VSS + d4) = *(const float4*)(vp + (size_t)r*HD + d4);
            }
        }
        __syncthreads();

        // ---- S = Q K^T (4x4 per thread), float4-vectorized over k ----
        float s[4][4];
#pragma unroll
        for (int i = 0; i < 4; i++)
#pragma unroll
            for (int j = 0; j < 4; j++) s[i][j] = 0.0f;

#pragma unroll
        for (int kk = 0; kk < HD; kk += 4) {
            float qa[4][4], ka[4][4];
#pragma unroll
            for (int i = 0; i < 4; i++) {
                float4 t4 = *(const float4*)(Qs + (r0+i)*QSS + kk);
                qa[i][0]=t4.x; qa[i][1]=t4.y; qa[i][2]=t4.z; qa[i][3]=t4.w;
            }
#pragma unroll
            for (int mm = 0; mm < 4; mm++) {
                float4 t4 = *(const float4*)(Kt + (kk+mm)*KTS + c0);
                ka[mm][0]=t4.x; ka[mm][1]=t4.y; ka[mm][2]=t4.z; ka[mm][3]=t4.w;
            }
#pragma unroll
            for (int i = 0; i < 4; i++)
#pragma unroll
                for (int j = 0; j < 4; j++)
                    s[i][j] += qa[i][0]*ka[0][j] + qa[i][1]*ka[1][j]
                             + qa[i][2]*ka[2][j] + qa[i][3]*ka[3][j];
        }

        // causal mask (diagonal tile only)
        if (t == qtile) {
#pragma unroll
            for (int i = 0; i < 4; i++)
#pragma unroll
                for (int j = 0; j < 4; j++)
                    if (c0 + j > r0 + i) s[i][j] = -1e30f;
        }

        // ---- online softmax: 16-lane shuffle reductions per row ----
#pragma unroll
        for (int i = 0; i < 4; i++) {
            float lm = fmaxf(fmaxf(s[i][0], s[i][1]), fmaxf(s[i][2], s[i][3]));
#pragma unroll
            for (int off = 8; off >= 1; off >>= 1)
                lm = fmaxf(lm, __shfl_xor_sync(0xffffffffu, lm, off, 16));
            float mnew = fmaxf(m_[i], lm);
            float alpha = __expf(m_[i] - mnew);

            s[i][0] = __expf(s[i][0] - mnew);
            s[i][1] = __expf(s[i][1] - mnew);
            s[i][2] = __expf(s[i][2] - mnew);
            s[i][3] = __expf(s[i][3] - mnew);
            float ls = s[i][0] + s[i][1] + s[i][2] + s[i][3];
#pragma unroll
            for (int off = 8; off >= 1; off >>= 1)
                ls += __shfl_xor_sync(0xffffffffu, ls, off, 16);

            m_[i] = mnew;
            l_[i] = l_[i]*alpha + ls;
            o[i][0] *= alpha; o[i][1] *= alpha; o[i][2] *= alpha; o[i][3] *= alpha;

            *(float4*)(Ps + (r0+i)*PSS + c0) = make_float4(s[i][0], s[i][1], s[i][2], s[i][3]);
        }
        __syncwarp();   // Ps rows are produced+consumed within the same half-warp group

        // ---- O += P V, float4-vectorized over c ----
#pragma unroll
        for (int cc = 0; cc < 64; cc += 4) {
            float pa[4][4], va[4][4];
#pragma unroll
            for (int i = 0; i < 4; i++) {
                float4 t4 = *(const float4*)(Ps + (r0+i)*PSS + cc);
                pa[i][0]=t4.x; pa[i][1]=t4.y; pa[i][2]=t4.z; pa[i][3]=t4.w;
            }
#pragma unroll
            for (int mm = 0; mm < 4; mm++) {
                float4 t4 = *(const float4*)(Vs + (cc+mm)*VSS + c0);
                va[mm][0]=t4.x; va[mm][1]=t4.y; va[mm][2]=t4.z; va[mm][3]=t4.w;
            }
#pragma unroll
            for (int i = 0; i < 4; i++)
#pragma unroll
                for (int j = 0; j < 4; j++)
                    o[i][j] += pa[i][0]*va[0][j] + pa[i][1]*va[1][j]
                             + pa[i][2]*va[2][j] + pa[i][3]*va[3][j];
        }
        __syncwarp();   // done reading Ps before next-iteration overwrite
    }

    // ---- normalize + store ----
#pragma unroll
    for (int i = 0; i < 4; i++) {
        float inv = 1.0f / l_[i];
        float4 r;
        r.x = o[i][0]*inv; r.y = o[i][1]*inv; r.z = o[i][2]*inv; r.w = o[i][3]*inv;
        *(float4*)(go + ((size_t)(b*TDIM + qbase + r0 + i))*CDIM + h*HD + c0) = r;
    }
}

// =========================================================================
// launch
// =========================================================================
extern "C" void kernel_launch(void* const* d_in, const int* in_sizes, int n_in,
                              void* d_out, int out_size)
{
    const float* x  = (const float*)d_in[0];
    const float* Wq = (const float*)d_in[1];
    const float* bq = (const float*)d_in[2];
    const float* Wk = (const float*)d_in[3];
    const float* bk = (const float*)d_in[4];
    const float* Wv = (const float*)d_in[5];
    const float* bv = (const float*)d_in[6];
    const float* Wo = (const float*)d_in[7];
    const float* bo = (const float*)d_in[8];
    float* out = (float*)d_out;

    float *qp, *kp, *vp, *ap;
    cudaGetSymbolAddress((void**)&qp, g_q);
    cudaGetSymbolAddress((void**)&kp, g_k);
    cudaGetSymbolAddress((void**)&vp, g_v);
    cudaGetSymbolAddress((void**)&ap, g_att);

    // Q = x @ Wq + bq   (4096 x 1024 x 1024)
    sgemm_bias_kernel<128,128,8,8,8><<<dim3(CDIM/128, MROWS/128), 256>>>(
        x, Wq, bq, qp, MROWS, CDIM, CDIM);
    // K = x @ Wk + bk, V = x @ Wv + bv   (4096 x 64 x 1024)
    sgemm_bias_kernel<64,64,16,4,4><<<dim3(HD/64, MROWS/64), 256>>>(
        x, Wk, bk, kp, MROWS, HD, CDIM);
    sgemm_bias_kernel<64,64,16,4,4><<<dim3(HD/64, MROWS/64), 256>>>(
        x, Wv, bv, vp, MROWS, HD, CDIM);

    // RoPE on q and k
    {
        int total = BDIM*TDIM*(NH+1)*(HD/2);
        rope_kernel<<<(total + 255)/256, 256>>>(qp, kp);
    }

    // causal MQA attention
    cudaFuncSetAttribute(attn_kernel, cudaFuncAttributeMaxDynamicSharedMemorySize,
                         ATT_SMEM_BYTES);
    attn_kernel<<<dim3(TDIM/64, NH, BDIM), 256, ATT_SMEM_BYTES>>>(qp, kp, vp, ap);

    // out = att @ Wo + bo
    sgemm_bias_kernel<128,128,8,8,8><<<dim3(CDIM/128, MROWS/128), 256>>>(
        ap, Wo, bo, out, MROWS, CDIM, CDIM);
}

// round 6
// speedup vs baseline: 1.3810x; 1.3810x over previous
#include <cuda_runtime.h>
#include <math.h>
#include <cstdint>

// Problem dims (fixed)
#define BDIM 2
#define TDIM 2048
#define CDIM 1024
#define NH   16
#define HD   64
#define MROWS (BDIM*TDIM)   // 4096

// ---------------- device scratch (no allocations allowed) ----------------
__device__ float g_q[(size_t)MROWS*CDIM];   // q after rope
__device__ float g_k[(size_t)MROWS*HD];
__device__ float g_v[(size_t)MROWS*HD];
__device__ float g_att[(size_t)MROWS*CDIM];

// ======================= helpers =========================================
__device__ __forceinline__ float to_tf32(float x) {
    float r; asm("cvt.rna.tf32.f32 %0, %1;" : "=f"(r) : "f"(x)); return r;
}
__device__ __forceinline__ void mma_tf32(float* c,
    uint32_t a0, uint32_t a1, uint32_t a2, uint32_t a3,
    uint32_t b0, uint32_t b1)
{
    asm volatile(
        "mma.sync.aligned.m16n8k8.row.col.f32.tf32.tf32.f32 "
        "{%0,%1,%2,%3}, {%4,%5,%6,%7}, {%8,%9}, {%0,%1,%2,%3};"
        : "+f"(c[0]), "+f"(c[1]), "+f"(c[2]), "+f"(c[3])
        : "r"(a0), "r"(a1), "r"(a2), "r"(a3), "r"(b0), "r"(b1));
}

// =========================================================================
// Tensor-core tf32 GEMM via mma.sync:
//   C[M,N] = tf32(A[M,K]) @ tf32(B[K,N]) + bias[N]
// CTA tile 128 x BN, BK=16, 256 threads = 8 warps (2 m x 4 n).
// Warp tile 64 x (BN/4). Double-buffered smem.
// =========================================================================
template<int BN>
__global__ void __launch_bounds__(256)
tc_gemm_kernel(const float* __restrict__ A, const float* __restrict__ B,
               const float* __restrict__ bias, float* __restrict__ C,
               int M, int N, int K)
{
    constexpr int BM  = 128;
    constexpr int BK  = 16;
    constexpr int AS  = BK + 4;       // As row stride (floats): 20, conflict-free frag reads
    constexpr int BNS = BN + 8;       // Bs row stride: conflict-free frag reads
    constexpr int A_FLOATS = BM * AS;         // per buffer
    constexpr int B_FLOATS = BK * BNS;
    constexpr int A_F4 = BM * BK / (4 * 256); // float4 loads per thread: 2
    constexpr int B_F4 = BK * BN / (4 * 256); // 2 (BN=128) or 1 (BN=64)
    constexpr int NT   = BN / 32;             // n8 tiles per warp: 4 or 2
    constexpr int WN   = BN / 4;              // warp n extent

    extern __shared__ float sm[];
    float* As = sm;                        // [2][BM][AS]
    float* Bs = sm + 2 * A_FLOATS;         // [2][BK][BNS]

    const int tid   = threadIdx.x;
    const int lane  = tid & 31;
    const int w     = tid >> 5;
    const int warpM = w & 1;               // 0..1
    const int warpN = w >> 1;              // 0..3
    const int g     = lane >> 2;           // groupID (row within frag)
    const int qd    = lane & 3;            // threadID_in_group (k index)
    const int rowBase = blockIdx.y * BM;
    const int colBase = blockIdx.x * BN;

    // per-thread global/smem slots
    int ar[A_F4]; int akq[A_F4];
#pragma unroll
    for (int t = 0; t < A_F4; t++) {
        int idx = tid + t * 256;
        ar[t] = idx >> 2; akq[t] = (idx & 3) * 4;
    }
    int br[B_F4]; int bc4[B_F4];
#pragma unroll
    for (int t = 0; t < B_F4; t++) {
        int idx = tid + t * 256;
        br[t] = idx / (BN / 4); bc4[t] = (idx % (BN / 4)) * 4;
    }

    const int NI = K / BK;

    float acc[4][NT][4];
#pragma unroll
    for (int mt = 0; mt < 4; mt++)
#pragma unroll
        for (int nt = 0; nt < NT; nt++)
#pragma unroll
            for (int i = 0; i < 4; i++) acc[mt][nt][i] = 0.0f;

    float4 aR[A_F4], bR[B_F4];

    auto fetch = [&](int j) {
#pragma unroll
        for (int t = 0; t < A_F4; t++)
            aR[t] = *(const float4*)&A[(size_t)(rowBase + ar[t]) * K + j * BK + akq[t]];
#pragma unroll
        for (int t = 0; t < B_F4; t++)
            bR[t] = *(const float4*)&B[(size_t)(j * BK + br[t]) * N + colBase + bc4[t]];
    };
    auto stage = [&](int buf) {
        float* Ab = As + buf * A_FLOATS;
        float* Bb = Bs + buf * B_FLOATS;
#pragma unroll
        for (int t = 0; t < A_F4; t++) {
            float4 v = aR[t];
            v.x = to_tf32(v.x); v.y = to_tf32(v.y); v.z = to_tf32(v.z); v.w = to_tf32(v.w);
            *(float4*)&Ab[ar[t] * AS + akq[t]] = v;
        }
#pragma unroll
        for (int t = 0; t < B_F4; t++) {
            float4 v = bR[t];
            v.x = to_tf32(v.x); v.y = to_tf32(v.y); v.z = to_tf32(v.z); v.w = to_tf32(v.w);
            *(float4*)&Bb[br[t] * BNS + bc4[t]] = v;
        }
    };

    fetch(0); stage(0);
    __syncthreads();

    for (int j = 0; j < NI; j++) {
        const int buf = j & 1;
        if (j + 1 < NI) fetch(j + 1);

        const float* Ab = As + buf * A_FLOATS;
        const float* Bb = Bs + buf * B_FLOATS;
#pragma unroll
        for (int kk = 0; kk < BK; kk += 8) {
            uint32_t afr[4][4];
#pragma unroll
            for (int mt = 0; mt < 4; mt++) {
                const int m0 = warpM * 64 + mt * 16;
                afr[mt][0] = __float_as_uint(Ab[(m0 + g    ) * AS + kk + qd    ]);
                afr[mt][1] = __float_as_uint(Ab[(m0 + g + 8) * AS + kk + qd    ]);
                afr[mt][2] = __float_as_uint(Ab[(m0 + g    ) * AS + kk + qd + 4]);
                afr[mt][3] = __float_as_uint(Ab[(m0 + g + 8) * AS + kk + qd + 4]);
            }
            uint32_t bfr[NT][2];
#pragma unroll
            for (int nt = 0; nt < NT; nt++) {
                const int n0 = warpN * WN + nt * 8;
                bfr[nt][0] = __float_as_uint(Bb[(kk + qd    ) * BNS + n0 + g]);
                bfr[nt][1] = __float_as_uint(Bb[(kk + qd + 4) * BNS + n0 + g]);
            }
#pragma unroll
            for (int mt = 0; mt < 4; mt++)
#pragma unroll
                for (int nt = 0; nt < NT; nt++)
                    mma_tf32(acc[mt][nt], afr[mt][0], afr[mt][1], afr[mt][2], afr[mt][3],
                             bfr[nt][0], bfr[nt][1]);
        }

        if (j + 1 < NI) {
            stage(buf ^ 1);
            __syncthreads();
        }
    }

    // epilogue: bias + store (float2 per fragment row)
#pragma unroll
    for (int mt = 0; mt < 4; mt++) {
        const int row0 = rowBase + warpM * 64 + mt * 16 + g;
#pragma unroll
        for (int nt = 0; nt < NT; nt++) {
            const int c = colBase + warpN * WN + nt * 8 + qd * 2;
            const float b0 = bias[c], b1 = bias[c + 1];
            float2 v0 = make_float2(acc[mt][nt][0] + b0, acc[mt][nt][1] + b1);
            float2 v1 = make_float2(acc[mt][nt][2] + b0, acc[mt][nt][3] + b1);
            *(float2*)&C[(size_t)row0 * N + c] = v0;
            *(float2*)&C[(size_t)(row0 + 8) * N + c] = v1;
        }
    }
}

// =========================================================================
// RoPE: in-place on q (B,T,H,HD) and k (B,T,1,HD).
// =========================================================================
__global__ void rope_kernel(float* __restrict__ q, float* __restrict__ k)
{
    const int total = BDIM*TDIM*(NH+1)*(HD/2);
    int idx = blockIdx.x*blockDim.x + threadIdx.x;
    if (idx >= total) return;
    int pr   = idx & 31;
    int rest = idx >> 5;
    int hh   = rest % (NH+1);
    int bt   = rest / (NH+1);
    int t    = bt & (TDIM-1);

    float inv_freq = expf(-(float)pr * (9.2103403719761836f / 32.0f));
    float ang = (float)t * inv_freq;
    float sn, cs;
    sincosf(ang, &sn, &cs);

    float* base = (hh < NH) ? (q + (size_t)bt*CDIM + hh*HD)
                            : (k + (size_t)bt*HD);
    float t1 = base[pr];
    float t2 = base[pr + 32];
    base[pr]      = t1*cs + t2*sn;
    base[pr + 32] = t1*sn - t2*cs;
}

// =========================================================================
// Causal MQA flash attention (fp32 SIMT). BQ=BKV=64, HD=64, 256 threads.
// =========================================================================
#define QSS 68
#define KTS 68
#define VSS 64
#define PSS 68
#define ATT_SMEM_FLOATS (64*QSS + 64*KTS + 64*VSS + 64*PSS)
#define ATT_SMEM_BYTES  (ATT_SMEM_FLOATS*4)

__global__ void __launch_bounds__(256)
attn_kernel(const float* __restrict__ gq, const float* __restrict__ gk,
            const float* __restrict__ gv, float* __restrict__ go)
{
    extern __shared__ float sm[];
    float* Qs = sm;
    float* Kt = Qs + 64*QSS;
    float* Vs = Kt + 64*KTS;
    float* Ps = Vs + 64*VSS;

    const int qtile = blockIdx.x;
    const int h     = blockIdx.y;
    const int b     = blockIdx.z;
    const int tid   = threadIdx.x;
    const int tc    = tid & 15;
    const int tr    = tid >> 4;
    const int r0    = tr*4, c0 = tc*4;
    const int qbase = qtile*64;

    {
        const float* qp = gq + ((size_t)(b*TDIM + qbase))*CDIM + h*HD;
#pragma unroll
        for (int i = 0; i < 4; i++) {
            int idx = tid + i*256;
            int r = idx >> 4, d4 = (idx & 15) << 2;
            float4 v = *(const float4*)(qp + (size_t)r*CDIM + d4);
            Qs[r*QSS + d4+0] = v.x*0.125f;
            Qs[r*QSS + d4+1] = v.y*0.125f;
            Qs[r*QSS + d4+2] = v.z*0.125f;
            Qs[r*QSS + d4+3] = v.w*0.125f;
        }
    }

    float o[4][4];
    float m_[4], l_[4];
#pragma unroll
    for (int i = 0; i < 4; i++) {
        m_[i] = -1e30f; l_[i] = 0.0f;
#pragma unroll
        for (int j = 0; j < 4; j++) o[i][j] = 0.0f;
    }

    const int ntiles = qtile + 1;
    for (int t = 0; t < ntiles; t++) {
        const int kvbase = t*64;
        __syncthreads();
        {
            const float* kp = gk + ((size_t)(b*TDIM + kvbase))*HD;
#pragma unroll
            for (int i = 0; i < 16; i++) {
                int idx = tid + i*256;
                int d = idx & 63, rk = idx >> 6;
                Kt[d*KTS + rk] = kp[rk*HD + d];
            }
            const float* vp = gv + ((size_t)(b*TDIM + kvbase))*HD;
#pragma unroll
            for (int i = 0; i < 4; i++) {
                int idx = tid + i*256;
                int r = idx >> 4, d4 = (idx & 15) << 2;
                *(float4*)(Vs + r*VSS + d4) = *(const float4*)(vp + (size_t)r*HD + d4);
            }
        }
        __syncthreads();

        float s[4][4];
#pragma unroll
        for (int i = 0; i < 4; i++)
#pragma unroll
            for (int j = 0; j < 4; j++) s[i][j] = 0.0f;

#pragma unroll
        for (int kk = 0; kk < HD; kk += 4) {
            float qa[4][4], ka[4][4];
#pragma unroll
            for (int i = 0; i < 4; i++) {
                float4 t4 = *(const float4*)(Qs + (r0+i)*QSS + kk);
                qa[i][0]=t4.x; qa[i][1]=t4.y; qa[i][2]=t4.z; qa[i][3]=t4.w;
            }
#pragma unroll
            for (int mm = 0; mm < 4; mm++) {
                float4 t4 = *(const float4*)(Kt + (kk+mm)*KTS + c0);
                ka[mm][0]=t4.x; ka[mm][1]=t4.y; ka[mm][2]=t4.z; ka[mm][3]=t4.w;
            }
#pragma unroll
            for (int i = 0; i < 4; i++)
#pragma unroll
                for (int j = 0; j < 4; j++)
                    s[i][j] += qa[i][0]*ka[0][j] + qa[i][1]*ka[1][j]
                             + qa[i][2]*ka[2][j] + qa[i][3]*ka[3][j];
        }

        if (t == qtile) {
#pragma unroll
            for (int i = 0; i < 4; i++)
#pragma unroll
                for (int j = 0; j < 4; j++)
                    if (c0 + j > r0 + i) s[i][j] = -1e30f;
        }

#pragma unroll
        for (int i = 0; i < 4; i++) {
            float lm = fmaxf(fmaxf(s[i][0], s[i][1]), fmaxf(s[i][2], s[i][3]));
#pragma unroll
            for (int off = 8; off >= 1; off >>= 1)
                lm = fmaxf(lm, __shfl_xor_sync(0xffffffffu, lm, off, 16));
            float mnew = fmaxf(m_[i], lm);
            float alpha = __expf(m_[i] - mnew);

            s[i][0] = __expf(s[i][0] - mnew);
            s[i][1] = __expf(s[i][1] - mnew);
            s[i][2] = __expf(s[i][2] - mnew);
            s[i][3] = __expf(s[i][3] - mnew);
            float ls = s[i][0] + s[i][1] + s[i][2] + s[i][3];
#pragma unroll
            for (int off = 8; off >= 1; off >>= 1)
                ls += __shfl_xor_sync(0xffffffffu, ls, off, 16);

            m_[i] = mnew;
            l_[i] = l_[i]*alpha + ls;
            o[i][0] *= alpha; o[i][1] *= alpha; o[i][2] *= alpha; o[i][3] *= alpha;

            *(float4*)(Ps + (r0+i)*PSS + c0) = make_float4(s[i][0], s[i][1], s[i][2], s[i][3]);
        }
        __syncwarp();

#pragma unroll
        for (int cc = 0; cc < 64; cc += 4) {
            float pa[4][4], va[4][4];
#pragma unroll
            for (int i = 0; i < 4; i++) {
                float4 t4 = *(const float4*)(Ps + (r0+i)*PSS + cc);
                pa[i][0]=t4.x; pa[i][1]=t4.y; pa[i][2]=t4.z; pa[i][3]=t4.w;
            }
#pragma unroll
            for (int mm = 0; mm < 4; mm++) {
                float4 t4 = *(const float4*)(Vs + (cc+mm)*VSS + c0);
                va[mm][0]=t4.x; va[mm][1]=t4.y; va[mm][2]=t4.z; va[mm][3]=t4.w;
            }
#pragma unroll
            for (int i = 0; i < 4; i++)
#pragma unroll
                for (int j = 0; j < 4; j++)
                    o[i][j] += pa[i][0]*va[0][j] + pa[i][1]*va[1][j]
                             + pa[i][2]*va[2][j] + pa[i][3]*va[3][j];
        }
        __syncwarp();
    }

#pragma unroll
    for (int i = 0; i < 4; i++) {
        float inv = 1.0f / l_[i];
        float4 r;
        r.x = o[i][0]*inv; r.y = o[i][1]*inv; r.z = o[i][2]*inv; r.w = o[i][3]*inv;
        *(float4*)(go + ((size_t)(b*TDIM + qbase + r0 + i))*CDIM + h*HD + c0) = r;
    }
}

// =========================================================================
// launch
// =========================================================================
extern "C" void kernel_launch(void* const* d_in, const int* in_sizes, int n_in,
                              void* d_out, int out_size)
{
    const float* x  = (const float*)d_in[0];
    const float* Wq = (const float*)d_in[1];
    const float* bq = (const float*)d_in[2];
    const float* Wk = (const float*)d_in[3];
    const float* bk = (const float*)d_in[4];
    const float* Wv = (const float*)d_in[5];
    const float* bv = (const float*)d_in[6];
    const float* Wo = (const float*)d_in[7];
    const float* bo = (const float*)d_in[8];
    float* out = (float*)d_out;

    float *qp, *kp, *vp, *ap;
    cudaGetSymbolAddress((void**)&qp, g_q);
    cudaGetSymbolAddress((void**)&kp, g_k);
    cudaGetSymbolAddress((void**)&vp, g_v);
    cudaGetSymbolAddress((void**)&ap, g_att);

    // smem sizes (floats): 2*(128*20) + 2*(16*(BN+8))
    constexpr int SM128 = (2*(128*20) + 2*(16*136)) * 4;   // 37888 B
    constexpr int SM64  = (2*(128*20) + 2*(16*72))  * 4;   // 29696 B
    cudaFuncSetAttribute(tc_gemm_kernel<128>,
        cudaFuncAttributeMaxDynamicSharedMemorySize, SM128);
    cudaFuncSetAttribute(tc_gemm_kernel<64>,
        cudaFuncAttributeMaxDynamicSharedMemorySize, SM64);

    // Q = x @ Wq + bq   (4096 x 1024 x 1024)
    tc_gemm_kernel<128><<<dim3(CDIM/128, MROWS/128), 256, SM128>>>(
        x, Wq, bq, qp, MROWS, CDIM, CDIM);
    // K,V = x @ Wk/Wv + b (4096 x 64 x 1024)
    tc_gemm_kernel<64><<<dim3(1, MROWS/128), 256, SM64>>>(
        x, Wk, bk, kp, MROWS, HD, CDIM);
    tc_gemm_kernel<64><<<dim3(1, MROWS/128), 256, SM64>>>(
        x, Wv, bv, vp, MROWS, HD, CDIM);

    // RoPE on q and k
    {
        int total = BDIM*TDIM*(NH+1)*(HD/2);
        rope_kernel<<<(total + 255)/256, 256>>>(qp, kp);
    }

    // causal MQA attention (fp32 SIMT)
    cudaFuncSetAttribute(attn_kernel, cudaFuncAttributeMaxDynamicSharedMemorySize,
                         ATT_SMEM_BYTES);
    attn_kernel<<<dim3(TDIM/64, NH, BDIM), 256, ATT_SMEM_BYTES>>>(qp, kp, vp, ap);

    // out = att @ Wo + bo
    tc_gemm_kernel<128><<<dim3(CDIM/128, MROWS/128), 256, SM128>>>(
        ap, Wo, bo, out, MROWS, CDIM, CDIM);
}

// round 7
// speedup vs baseline: 2.5681x; 1.8596x over previous
#include <cuda_runtime.h>
#include <math.h>
#include <cstdint>

// Problem dims (fixed)
#define BDIM 2
#define TDIM 2048
#define CDIM 1024
#define NH   16
#define HD   64
#define MROWS (BDIM*TDIM)   // 4096

// ---------------- device scratch (no allocations allowed) ----------------
__device__ float g_q[(size_t)MROWS*CDIM];   // q after rope
__device__ float g_k[(size_t)MROWS*HD];
__device__ float g_v[(size_t)MROWS*HD];
__device__ float g_att[(size_t)MROWS*CDIM];

// ======================= helpers =========================================
__device__ __forceinline__ float to_tf32(float x) {
    float r; asm("cvt.rna.tf32.f32 %0, %1;" : "=f"(r) : "f"(x)); return r;
}
__device__ __forceinline__ void mma_tf32(float* c,
    uint32_t a0, uint32_t a1, uint32_t a2, uint32_t a3,
    uint32_t b0, uint32_t b1)
{
    asm volatile(
        "mma.sync.aligned.m16n8k8.row.col.f32.tf32.tf32.f32 "
        "{%0,%1,%2,%3}, {%4,%5,%6,%7}, {%8,%9}, {%0,%1,%2,%3};"
        : "+f"(c[0]), "+f"(c[1]), "+f"(c[2]), "+f"(c[3])
        : "r"(a0), "r"(a1), "r"(a2), "r"(a3), "r"(b0), "r"(b1));
}

// =========================================================================
// Tensor-core tf32 GEMM via mma.sync:
//   C[M,N] = tf32(A[M,K]) @ tf32(B[K,N]) + bias[N]
// CTA tile 128 x BN, BK=16, 256 threads = 8 warps (2 m x 4 n).
// =========================================================================
template<int BN>
__global__ void __launch_bounds__(256)
tc_gemm_kernel(const float* __restrict__ A, const float* __restrict__ B,
               const float* __restrict__ bias, float* __restrict__ C,
               int M, int N, int K)
{
    constexpr int BM  = 128;
    constexpr int BK  = 16;
    constexpr int AS  = BK + 4;
    constexpr int BNS = BN + 8;
    constexpr int A_FLOATS = BM * AS;
    constexpr int B_FLOATS = BK * BNS;
    constexpr int A_F4 = BM * BK / (4 * 256);
    constexpr int B_F4 = BK * BN / (4 * 256);
    constexpr int NT   = BN / 32;
    constexpr int WN   = BN / 4;

    extern __shared__ float sm[];
    float* As = sm;
    float* Bs = sm + 2 * A_FLOATS;

    const int tid   = threadIdx.x;
    const int lane  = tid & 31;
    const int w     = tid >> 5;
    const int warpM = w & 1;
    const int warpN = w >> 1;
    const int g     = lane >> 2;
    const int qd    = lane & 3;
    const int rowBase = blockIdx.y * BM;
    const int colBase = blockIdx.x * BN;

    int ar[A_F4]; int akq[A_F4];
#pragma unroll
    for (int t = 0; t < A_F4; t++) {
        int idx = tid + t * 256;
        ar[t] = idx >> 2; akq[t] = (idx & 3) * 4;
    }
    int br[B_F4]; int bc4[B_F4];
#pragma unroll
    for (int t = 0; t < B_F4; t++) {
        int idx = tid + t * 256;
        br[t] = idx / (BN / 4); bc4[t] = (idx % (BN / 4)) * 4;
    }

    const int NI = K / BK;

    float acc[4][NT][4];
#pragma unroll
    for (int mt = 0; mt < 4; mt++)
#pragma unroll
        for (int nt = 0; nt < NT; nt++)
#pragma unroll
            for (int i = 0; i < 4; i++) acc[mt][nt][i] = 0.0f;

    float4 aR[A_F4], bR[B_F4];

    auto fetch = [&](int j) {
#pragma unroll
        for (int t = 0; t < A_F4; t++)
            aR[t] = *(const float4*)&A[(size_t)(rowBase + ar[t]) * K + j * BK + akq[t]];
#pragma unroll
        for (int t = 0; t < B_F4; t++)
            bR[t] = *(const float4*)&B[(size_t)(j * BK + br[t]) * N + colBase + bc4[t]];
    };
    auto stage = [&](int buf) {
        float* Ab = As + buf * A_FLOATS;
        float* Bb = Bs + buf * B_FLOATS;
#pragma unroll
        for (int t = 0; t < A_F4; t++) {
            float4 v = aR[t];
            v.x = to_tf32(v.x); v.y = to_tf32(v.y); v.z = to_tf32(v.z); v.w = to_tf32(v.w);
            *(float4*)&Ab[ar[t] * AS + akq[t]] = v;
        }
#pragma unroll
        for (int t = 0; t < B_F4; t++) {
            float4 v = bR[t];
            v.x = to_tf32(v.x); v.y = to_tf32(v.y); v.z = to_tf32(v.z); v.w = to_tf32(v.w);
            *(float4*)&Bb[br[t] * BNS + bc4[t]] = v;
        }
    };

    fetch(0); stage(0);
    __syncthreads();

    for (int j = 0; j < NI; j++) {
        const int buf = j & 1;
        if (j + 1 < NI) fetch(j + 1);

        const float* Ab = As + buf * A_FLOATS;
        const float* Bb = Bs + buf * B_FLOATS;
#pragma unroll
        for (int kk = 0; kk < BK; kk += 8) {
            uint32_t afr[4][4];
#pragma unroll
            for (int mt = 0; mt < 4; mt++) {
                const int m0 = warpM * 64 + mt * 16;
                afr[mt][0] = __float_as_uint(Ab[(m0 + g    ) * AS + kk + qd    ]);
                afr[mt][1] = __float_as_uint(Ab[(m0 + g + 8) * AS + kk + qd    ]);
                afr[mt][2] = __float_as_uint(Ab[(m0 + g    ) * AS + kk + qd + 4]);
                afr[mt][3] = __float_as_uint(Ab[(m0 + g + 8) * AS + kk + qd + 4]);
            }
            uint32_t bfr[NT][2];
#pragma unroll
            for (int nt = 0; nt < NT; nt++) {
                const int n0 = warpN * WN + nt * 8;
                bfr[nt][0] = __float_as_uint(Bb[(kk + qd    ) * BNS + n0 + g]);
                bfr[nt][1] = __float_as_uint(Bb[(kk + qd + 4) * BNS + n0 + g]);
            }
#pragma unroll
            for (int mt = 0; mt < 4; mt++)
#pragma unroll
                for (int nt = 0; nt < NT; nt++)
                    mma_tf32(acc[mt][nt], afr[mt][0], afr[mt][1], afr[mt][2], afr[mt][3],
                             bfr[nt][0], bfr[nt][1]);
        }

        if (j + 1 < NI) {
            stage(buf ^ 1);
            __syncthreads();
        }
    }

#pragma unroll
    for (int mt = 0; mt < 4; mt++) {
        const int row0 = rowBase + warpM * 64 + mt * 16 + g;
#pragma unroll
        for (int nt = 0; nt < NT; nt++) {
            const int c = colBase + warpN * WN + nt * 8 + qd * 2;
            const float b0 = bias[c], b1 = bias[c + 1];
            float2 v0 = make_float2(acc[mt][nt][0] + b0, acc[mt][nt][1] + b1);
            float2 v1 = make_float2(acc[mt][nt][2] + b0, acc[mt][nt][3] + b1);
            *(float2*)&C[(size_t)row0 * N + c] = v0;
            *(float2*)&C[(size_t)(row0 + 8) * N + c] = v1;
        }
    }
}

// K and V projections fused: blockIdx.z selects which weight/bias/output.
__global__ void __launch_bounds__(256)
tc_gemm_kv_kernel(const float* __restrict__ A,
                  const float* __restrict__ B0, const float* __restrict__ bias0,
                  float* __restrict__ C0,
                  const float* __restrict__ B1, const float* __restrict__ bias1,
                  float* __restrict__ C1,
                  int M, int N, int K)
{
    constexpr int BN  = 64;
    constexpr int BM  = 128;
    constexpr int BK  = 16;
    constexpr int AS  = BK + 4;
    constexpr int BNS = BN + 8;
    constexpr int A_FLOATS = BM * AS;
    constexpr int B_FLOATS = BK * BNS;
    constexpr int A_F4 = BM * BK / (4 * 256);
    constexpr int B_F4 = BK * BN / (4 * 256);
    constexpr int NT   = BN / 32;
    constexpr int WN   = BN / 4;

    const float* B    = blockIdx.z ? B1 : B0;
    const float* bias = blockIdx.z ? bias1 : bias0;
    float*       C    = blockIdx.z ? C1 : C0;

    extern __shared__ float sm[];
    float* As = sm;
    float* Bs = sm + 2 * A_FLOATS;

    const int tid   = threadIdx.x;
    const int lane  = tid & 31;
    const int w     = tid >> 5;
    const int warpM = w & 1;
    const int warpN = w >> 1;
    const int g     = lane >> 2;
    const int qd    = lane & 3;
    const int rowBase = blockIdx.y * BM;
    const int colBase = 0;

    int ar[A_F4]; int akq[A_F4];
#pragma unroll
    for (int t = 0; t < A_F4; t++) {
        int idx = tid + t * 256;
        ar[t] = idx >> 2; akq[t] = (idx & 3) * 4;
    }
    int br[B_F4]; int bc4[B_F4];
#pragma unroll
    for (int t = 0; t < B_F4; t++) {
        int idx = tid + t * 256;
        br[t] = idx / (BN / 4); bc4[t] = (idx % (BN / 4)) * 4;
    }

    const int NI = K / BK;

    float acc[4][NT][4];
#pragma unroll
    for (int mt = 0; mt < 4; mt++)
#pragma unroll
        for (int nt = 0; nt < NT; nt++)
#pragma unroll
            for (int i = 0; i < 4; i++) acc[mt][nt][i] = 0.0f;

    float4 aR[A_F4], bR[B_F4];

    auto fetch = [&](int j) {
#pragma unroll
        for (int t = 0; t < A_F4; t++)
            aR[t] = *(const float4*)&A[(size_t)(rowBase + ar[t]) * K + j * BK + akq[t]];
#pragma unroll
        for (int t = 0; t < B_F4; t++)
            bR[t] = *(const float4*)&B[(size_t)(j * BK + br[t]) * N + colBase + bc4[t]];
    };
    auto stage = [&](int buf) {
        float* Ab = As + buf * A_FLOATS;
        float* Bb = Bs + buf * B_FLOATS;
#pragma unroll
        for (int t = 0; t < A_F4; t++) {
            float4 v = aR[t];
            v.x = to_tf32(v.x); v.y = to_tf32(v.y); v.z = to_tf32(v.z); v.w = to_tf32(v.w);
            *(float4*)&Ab[ar[t] * AS + akq[t]] = v;
        }
#pragma unroll
        for (int t = 0; t < B_F4; t++) {
            float4 v = bR[t];
            v.x = to_tf32(v.x); v.y = to_tf32(v.y); v.z = to_tf32(v.z); v.w = to_tf32(v.w);
            *(float4*)&Bb[br[t] * BNS + bc4[t]] = v;
        }
    };

    fetch(0); stage(0);
    __syncthreads();

    for (int j = 0; j < NI; j++) {
        const int buf = j & 1;
        if (j + 1 < NI) fetch(j + 1);

        const float* Ab = As + buf * A_FLOATS;
        const float* Bb = Bs + buf * B_FLOATS;
#pragma unroll
        for (int kk = 0; kk < BK; kk += 8) {
            uint32_t afr[4][4];
#pragma unroll
            for (int mt = 0; mt < 4; mt++) {
                const int m0 = warpM * 64 + mt * 16;
                afr[mt][0] = __float_as_uint(Ab[(m0 + g    ) * AS + kk + qd    ]);
                afr[mt][1] = __float_as_uint(Ab[(m0 + g + 8) * AS + kk + qd    ]);
                afr[mt][2] = __float_as_uint(Ab[(m0 + g    ) * AS + kk + qd + 4]);
                afr[mt][3] = __float_as_uint(Ab[(m0 + g + 8) * AS + kk + qd + 4]);
            }
            uint32_t bfr[NT][2];
#pragma unroll
            for (int nt = 0; nt < NT; nt++) {
                const int n0 = warpN * WN + nt * 8;
                bfr[nt][0] = __float_as_uint(Bb[(kk + qd    ) * BNS + n0 + g]);
                bfr[nt][1] = __float_as_uint(Bb[(kk + qd + 4) * BNS + n0 + g]);
            }
#pragma unroll
            for (int mt = 0; mt < 4; mt++)
#pragma unroll
                for (int nt = 0; nt < NT; nt++)
                    mma_tf32(acc[mt][nt], afr[mt][0], afr[mt][1], afr[mt][2], afr[mt][3],
                             bfr[nt][0], bfr[nt][1]);
        }

        if (j + 1 < NI) {
            stage(buf ^ 1);
            __syncthreads();
        }
    }

#pragma unroll
    for (int mt = 0; mt < 4; mt++) {
        const int row0 = rowBase + warpM * 64 + mt * 16 + g;
#pragma unroll
        for (int nt = 0; nt < NT; nt++) {
            const int c = colBase + warpN * WN + nt * 8 + qd * 2;
            const float b0 = bias[c], b1 = bias[c + 1];
            float2 v0 = make_float2(acc[mt][nt][0] + b0, acc[mt][nt][1] + b1);
            float2 v1 = make_float2(acc[mt][nt][2] + b0, acc[mt][nt][3] + b1);
            *(float2*)&C[(size_t)row0 * N + c] = v0;
            *(float2*)&C[(size_t)(row0 + 8) * N + c] = v1;
        }
    }
}

// =========================================================================
// RoPE: in-place on q (B,T,H,HD) and k (B,T,1,HD).
// =========================================================================
__global__ void rope_kernel(float* __restrict__ q, float* __restrict__ k)
{
    const int total = BDIM*TDIM*(NH+1)*(HD/2);
    int idx = blockIdx.x*blockDim.x + threadIdx.x;
    if (idx >= total) return;
    int pr   = idx & 31;
    int rest = idx >> 5;
    int hh   = rest % (NH+1);
    int bt   = rest / (NH+1);
    int t    = bt & (TDIM-1);

    float inv_freq = expf(-(float)pr * (9.2103403719761836f / 32.0f));
    float ang = (float)t * inv_freq;
    float sn, cs;
    sincosf(ang, &sn, &cs);

    float* base = (hh < NH) ? (q + (size_t)bt*CDIM + hh*HD)
                            : (k + (size_t)bt*HD);
    float t1 = base[pr];
    float t2 = base[pr + 32];
    base[pr]      = t1*cs + t2*sn;
    base[pr + 32] = t1*sn - t2*cs;
}

// =========================================================================
// Tensor-core causal MQA flash attention.  BQ=BKV=64, HD=64.
// 128 threads = 4 warps; each warp owns 16 query rows (m16 per mma).
// S = Q K^T and O = P V via mma.sync tf32 m16n8k8.
// K/V staged in smem as k-paired float2 rows: row p = kk*4+qd holds pairs
// (x=elem k=kk*8+qd, y=elem k=kk*8+qd+4), so every B-fragment is one LDS.64.
// Stride 68 float2 -> bank = 8*qd + 2*g: conflict-free fragment loads.
// =========================================================================
#define KP2S 68                 // KtP/VsP row stride in float2
#define QPS  68                 // QP row stride in floats
#define ATT2_SMEM_BYTES ((2*32*KP2S*2 + 64*QPS) * 4)   // 52224

__global__ void __launch_bounds__(128)
attn_tc_kernel(const float* __restrict__ gq, const float* __restrict__ gk,
               const float* __restrict__ gv, float* __restrict__ go)
{
    extern __shared__ float sm[];
    float2* KtP = (float2*)sm;                    // [32][KP2S]
    float2* VsP = (float2*)(sm + 32*KP2S*2);      // [32][KP2S]
    float*  QP  = sm + 2*32*KP2S*2;               // [64][QPS]  Q staging, then P

    const int qtile = (gridDim.x - 1) - blockIdx.x;   // heavy blocks first
    const int h     = blockIdx.y;
    const int b     = blockIdx.z;
    const int tid   = threadIdx.x;
    const int lane  = tid & 31;
    const int w     = tid >> 5;
    const int g     = lane >> 2;     // fragment row within 8
    const int qd    = lane & 3;      // fragment k/col quad index
    const int r0    = w * 16;        // warp's query-row base (local)
    const int qbase = qtile * 64;

    // ---- stage Q (scaled by 1/8, tf32) ----
    {
        const float* qp = gq + ((size_t)(b*TDIM + qbase))*CDIM + h*HD;
#pragma unroll
        for (int i = 0; i < 8; i++) {
            int idx = tid + i*128;
            int r = idx >> 4, d4 = (idx & 15) << 2;
            float4 v = *(const float4*)(qp + (size_t)r*CDIM + d4);
            QP[r*QPS + d4+0] = to_tf32(v.x*0.125f);
            QP[r*QPS + d4+1] = to_tf32(v.y*0.125f);
            QP[r*QPS + d4+2] = to_tf32(v.z*0.125f);
            QP[r*QPS + d4+3] = to_tf32(v.w*0.125f);
        }
    }
    __syncthreads();

    // ---- Q fragments in registers (persist across kv tiles) ----
    uint32_t aQ[8][4];
#pragma unroll
    for (int kk = 0; kk < 8; kk++) {
        const int kb = kk*8;
        aQ[kk][0] = __float_as_uint(QP[(r0+g    )*QPS + kb + qd    ]);
        aQ[kk][1] = __float_as_uint(QP[(r0+g+8  )*QPS + kb + qd    ]);
        aQ[kk][2] = __float_as_uint(QP[(r0+g    )*QPS + kb + qd + 4]);
        aQ[kk][3] = __float_as_uint(QP[(r0+g+8  )*QPS + kb + qd + 4]);
    }

    float m_[2] = {-1e30f, -1e30f};
    float l_[2] = {0.0f, 0.0f};
    float oacc[8][4];
#pragma unroll
    for (int nt = 0; nt < 8; nt++)
#pragma unroll
        for (int i = 0; i < 4; i++) oacc[nt][i] = 0.0f;

    for (int t = 0; t <= qtile; t++) {
        __syncthreads();    // everyone done reading KtP/VsP (and QP as P)

        // ---- stage K tile: KtP[kk*4+qd'][c] = (K[c][kk*8+qd'], K[c][kk*8+qd'+4]) ----
        {
            const float* kp = gk + ((size_t)(b*TDIM + t*64))*HD;
#pragma unroll
            for (int it = 0; it < 4; it++) {
                int idx = tid + it*128;          // 512 tasks: c(64) x j(8)
                int c = idx & 63, j = idx >> 6;
                float4 v0 = *(const float4*)(kp + (size_t)c*HD + j*8);
                float4 v1 = *(const float4*)(kp + (size_t)c*HD + j*8 + 4);
                KtP[(4*j+0)*KP2S + c] = make_float2(to_tf32(v0.x), to_tf32(v1.x));
                KtP[(4*j+1)*KP2S + c] = make_float2(to_tf32(v0.y), to_tf32(v1.y));
                KtP[(4*j+2)*KP2S + c] = make_float2(to_tf32(v0.z), to_tf32(v1.z));
                KtP[(4*j+3)*KP2S + c] = make_float2(to_tf32(v0.w), to_tf32(v1.w));
            }
            // ---- stage V tile: VsP[kk*4+qd'][n] = (V[kk*8+qd'][n], V[kk*8+qd'+4][n]) ----
            const float* vp = gv + ((size_t)(b*TDIM + t*64))*HD;
#pragma unroll
            for (int it = 0; it < 16; it++) {
                int idx = tid + it*128;          // 2048 tasks: n(64) x p(32)
                int n = idx & 63, p = idx >> 6;
                int rlo = (p >> 2)*8 + (p & 3);
                float a = vp[(size_t)rlo*HD + n];
                float bb = vp[(size_t)(rlo+4)*HD + n];
                VsP[p*KP2S + n] = make_float2(to_tf32(a), to_tf32(bb));
            }
        }
        __syncthreads();

        // ---- S = Q K^T ----
        float sacc[8][4];
#pragma unroll
        for (int nt = 0; nt < 8; nt++)
#pragma unroll
            for (int i = 0; i < 4; i++) sacc[nt][i] = 0.0f;

#pragma unroll
        for (int kk = 0; kk < 8; kk++) {
            float2 bf[8];
#pragma unroll
            for (int nt = 0; nt < 8; nt++)
                bf[nt] = KtP[(kk*4+qd)*KP2S + nt*8 + g];
#pragma unroll
            for (int nt = 0; nt < 8; nt++)
                mma_tf32(sacc[nt], aQ[kk][0], aQ[kk][1], aQ[kk][2], aQ[kk][3],
                         __float_as_uint(bf[nt].x), __float_as_uint(bf[nt].y));
        }

        // ---- causal mask (diagonal tile only; local indices) ----
        if (t == qtile) {
            const int ra = r0 + g, rb = ra + 8;
#pragma unroll
            for (int nt = 0; nt < 8; nt++) {
                const int ca = nt*8 + qd*2;
                if (ca     > ra) sacc[nt][0] = -1e30f;
                if (ca + 1 > ra) sacc[nt][1] = -1e30f;
                if (ca     > rb) sacc[nt][2] = -1e30f;
                if (ca + 1 > rb) sacc[nt][3] = -1e30f;
            }
        }

        // ---- online softmax (rows g and g+8; quad-shuffle reductions) ----
#pragma unroll
        for (int rr = 0; rr < 2; rr++) {
            float lm = -1e30f;
#pragma unroll
            for (int nt = 0; nt < 8; nt++)
                lm = fmaxf(lm, fmaxf(sacc[nt][2*rr], sacc[nt][2*rr+1]));
            lm = fmaxf(lm, __shfl_xor_sync(0xffffffffu, lm, 1));
            lm = fmaxf(lm, __shfl_xor_sync(0xffffffffu, lm, 2));
            float mnew  = fmaxf(m_[rr], lm);
            float alpha = __expf(m_[rr] - mnew);

            float ls = 0.0f;
            float pe[8][2];
#pragma unroll
            for (int nt = 0; nt < 8; nt++) {
                pe[nt][0] = __expf(sacc[nt][2*rr]   - mnew);
                pe[nt][1] = __expf(sacc[nt][2*rr+1] - mnew);
                ls += pe[nt][0] + pe[nt][1];
            }
            ls += __shfl_xor_sync(0xffffffffu, ls, 1);
            ls += __shfl_xor_sync(0xffffffffu, ls, 2);

            m_[rr] = mnew;
            l_[rr] = l_[rr]*alpha + ls;
#pragma unroll
            for (int nt = 0; nt < 8; nt++) {
                oacc[nt][2*rr]   *= alpha;
                oacc[nt][2*rr+1] *= alpha;
                *(float2*)&QP[(r0 + g + rr*8)*QPS + nt*8 + qd*2] =
                    make_float2(to_tf32(pe[nt][0]), to_tf32(pe[nt][1]));
            }
        }
        __syncwarp();   // P rows are warp-local: written and read by this warp only

        // ---- O += P V ----
#pragma unroll
        for (int kk = 0; kk < 8; kk++) {
            const int kb = kk*8;
            uint32_t pa0 = __float_as_uint(QP[(r0+g  )*QPS + kb + qd    ]);
            uint32_t pa1 = __float_as_uint(QP[(r0+g+8)*QPS + kb + qd    ]);
            uint32_t pa2 = __float_as_uint(QP[(r0+g  )*QPS + kb + qd + 4]);
            uint32_t pa3 = __float_as_uint(QP[(r0+g+8)*QPS + kb + qd + 4]);
            float2 bv[8];
#pragma unroll
            for (int nt = 0; nt < 8; nt++)
                bv[nt] = VsP[(kk*4+qd)*KP2S + nt*8 + g];
#pragma unroll
            for (int nt = 0; nt < 8; nt++)
                mma_tf32(oacc[nt], pa0, pa1, pa2, pa3,
                         __float_as_uint(bv[nt].x), __float_as_uint(bv[nt].y));
        }
    }

    // ---- normalize + store ----
#pragma unroll
    for (int rr = 0; rr < 2; rr++) {
        const float inv = 1.0f / l_[rr];
        float* op = go + ((size_t)(b*TDIM + qbase + r0 + g + rr*8))*CDIM + h*HD;
#pragma unroll
        for (int nt = 0; nt < 8; nt++) {
            *(float2*)&op[nt*8 + qd*2] =
                make_float2(oacc[nt][2*rr]*inv, oacc[nt][2*rr+1]*inv);
        }
    }
}

// =========================================================================
// launch
// =========================================================================
extern "C" void kernel_launch(void* const* d_in, const int* in_sizes, int n_in,
                              void* d_out, int out_size)
{
    const float* x  = (const float*)d_in[0];
    const float* Wq = (const float*)d_in[1];
    const float* bq = (const float*)d_in[2];
    const float* Wk = (const float*)d_in[3];
    const float* bk = (const float*)d_in[4];
    const float* Wv = (const float*)d_in[5];
    const float* bv = (const float*)d_in[6];
    const float* Wo = (const float*)d_in[7];
    const float* bo = (const float*)d_in[8];
    float* out = (float*)d_out;

    float *qp, *kp, *vp, *ap;
    cudaGetSymbolAddress((void**)&qp, g_q);
    cudaGetSymbolAddress((void**)&kp, g_k);
    cudaGetSymbolAddress((void**)&vp, g_v);
    cudaGetSymbolAddress((void**)&ap, g_att);

    constexpr int SM128 = (2*(128*20) + 2*(16*136)) * 4;   // 37888 B
    constexpr int SM64  = (2*(128*20) + 2*(16*72))  * 4;   // 29696 B
    cudaFuncSetAttribute(tc_gemm_kernel<128>,
        cudaFuncAttributeMaxDynamicSharedMemorySize, SM128);
    cudaFuncSetAttribute(tc_gemm_kv_kernel,
        cudaFuncAttributeMaxDynamicSharedMemorySize, SM64);
    cudaFuncSetAttribute(attn_tc_kernel,
        cudaFuncAttributeMaxDynamicSharedMemorySize, ATT2_SMEM_BYTES);

    // Q = x @ Wq + bq   (4096 x 1024 x 1024)
    tc_gemm_kernel<128><<<dim3(CDIM/128, MROWS/128), 256, SM128>>>(
        x, Wq, bq, qp, MROWS, CDIM, CDIM);
    // K,V = x @ Wk/Wv + b fused in one launch (z selects)
    tc_gemm_kv_kernel<<<dim3(1, MROWS/128, 2), 256, SM64>>>(
        x, Wk, bk, kp, Wv, bv, vp, MROWS, HD, CDIM);

    // RoPE on q and k
    {
        int total = BDIM*TDIM*(NH+1)*(HD/2);
        rope_kernel<<<(total + 255)/256, 256>>>(qp, kp);
    }

    // causal MQA attention (tensor cores)
    attn_tc_kernel<<<dim3(TDIM/64, NH, BDIM), 128, ATT2_SMEM_BYTES>>>(qp, kp, vp, ap);

    // out = att @ Wo + bo
    tc_gemm_kernel<128><<<dim3(CDIM/128, MROWS/128), 256, SM128>>>(
        ap, Wo, bo, out, MROWS, CDIM, CDIM);
}

// round 8
// speedup vs baseline: 3.2595x; 1.2692x over previous
#include <cuda_runtime.h>
#include <math.h>
#include <cstdint>

// Problem dims (fixed)
#define BDIM 2
#define TDIM 2048
#define CDIM 1024
#define NH   16
#define HD   64
#define MROWS (BDIM*TDIM)   // 4096

// ---------------- device scratch (no allocations allowed) ----------------
__device__ float g_q[(size_t)MROWS*CDIM];   // q after rope (natural layout)
__device__ float g_k[(size_t)MROWS*HD];     // k pre-rope (natural, gemm out)
__device__ float g_k2[(size_t)MROWS*HD];    // k post-rope, PAIRED-TRANSPOSED per 64-row tile
__device__ float g_v[(size_t)MROWS*HD];     // v PAIRED per 64-row tile (gemm writes directly)
__device__ float g_att[(size_t)MROWS*CDIM];

// Paired layouts (per 64-row kv tile, tile gt = global_row>>6):
//   K2[gt][p][c] (float2) = ( K[c][d], K[c][d+4] ),  p=((d>>3)<<2)|(d&3), comp=(d>>2)&1
//   V2[gt][p][n] (float2) = ( V[r][n], V[r+4][n] ),  p=((r>>3)<<2)|(r&3), comp=(r>>2)&1
// Both tiles are 32 rows x 64 float2 = 16KB, rows 512B contiguous (cp.async friendly).

// ======================= helpers =========================================
__device__ __forceinline__ float to_tf32(float x) {
    float r; asm("cvt.rna.tf32.f32 %0, %1;" : "=f"(r) : "f"(x)); return r;
}
__device__ __forceinline__ void mma_tf32(float* c,
    uint32_t a0, uint32_t a1, uint32_t a2, uint32_t a3,
    uint32_t b0, uint32_t b1)
{
    asm volatile(
        "mma.sync.aligned.m16n8k8.row.col.f32.tf32.tf32.f32 "
        "{%0,%1,%2,%3}, {%4,%5,%6,%7}, {%8,%9}, {%0,%1,%2,%3};"
        : "+f"(c[0]), "+f"(c[1]), "+f"(c[2]), "+f"(c[3])
        : "r"(a0), "r"(a1), "r"(a2), "r"(a3), "r"(b0), "r"(b1));
}
__device__ __forceinline__ uint32_t smem_u32(const void* p) {
    uint32_t a;
    asm("{ .reg .u64 t; cvta.to.shared.u64 t, %1; cvt.u32.u64 %0, t; }"
        : "=r"(a) : "l"(p));
    return a;
}
#define CP_ASYNC16(dst_u32, src_ptr) \
    asm volatile("cp.async.cg.shared.global [%0], [%1], 16;" \
        :: "r"(dst_u32), "l"(src_ptr) : "memory")
#define CP_COMMIT() asm volatile("cp.async.commit_group;" ::: "memory")
#define CP_WAIT0()  asm volatile("cp.async.wait_group 0;"  ::: "memory")

// =========================================================================
// Tensor-core tf32 GEMM via mma.sync:
//   C[M,N] = tf32(A[M,K]) @ tf32(B[K,N]) + bias[N]
// CTA tile 128 x BN, BK=16, 256 threads = 8 warps (2 m x 4 n).
// =========================================================================
template<int BN>
__global__ void __launch_bounds__(256)
tc_gemm_kernel(const float* __restrict__ A, const float* __restrict__ B,
               const float* __restrict__ bias, float* __restrict__ C,
               int M, int N, int K)
{
    constexpr int BM  = 128;
    constexpr int BK  = 16;
    constexpr int AS  = BK + 4;
    constexpr int BNS = BN + 8;
    constexpr int A_FLOATS = BM * AS;
    constexpr int B_FLOATS = BK * BNS;
    constexpr int A_F4 = BM * BK / (4 * 256);
    constexpr int B_F4 = BK * BN / (4 * 256);
    constexpr int NT   = BN / 32;
    constexpr int WN   = BN / 4;

    extern __shared__ float sm[];
    float* As = sm;
    float* Bs = sm + 2 * A_FLOATS;

    const int tid   = threadIdx.x;
    const int lane  = tid & 31;
    const int w     = tid >> 5;
    const int warpM = w & 1;
    const int warpN = w >> 1;
    const int g     = lane >> 2;
    const int qd    = lane & 3;
    const int rowBase = blockIdx.y * BM;
    const int colBase = blockIdx.x * BN;

    int ar[A_F4]; int akq[A_F4];
#pragma unroll
    for (int t = 0; t < A_F4; t++) {
        int idx = tid + t * 256;
        ar[t] = idx >> 2; akq[t] = (idx & 3) * 4;
    }
    int br[B_F4]; int bc4[B_F4];
#pragma unroll
    for (int t = 0; t < B_F4; t++) {
        int idx = tid + t * 256;
        br[t] = idx / (BN / 4); bc4[t] = (idx % (BN / 4)) * 4;
    }

    const int NI = K / BK;

    float acc[4][NT][4];
#pragma unroll
    for (int mt = 0; mt < 4; mt++)
#pragma unroll
        for (int nt = 0; nt < NT; nt++)
#pragma unroll
            for (int i = 0; i < 4; i++) acc[mt][nt][i] = 0.0f;

    float4 aR[A_F4], bR[B_F4];

    auto fetch = [&](int j) {
#pragma unroll
        for (int t = 0; t < A_F4; t++)
            aR[t] = *(const float4*)&A[(size_t)(rowBase + ar[t]) * K + j * BK + akq[t]];
#pragma unroll
        for (int t = 0; t < B_F4; t++)
            bR[t] = *(const float4*)&B[(size_t)(j * BK + br[t]) * N + colBase + bc4[t]];
    };
    auto stage = [&](int buf) {
        float* Ab = As + buf * A_FLOATS;
        float* Bb = Bs + buf * B_FLOATS;
#pragma unroll
        for (int t = 0; t < A_F4; t++) {
            float4 v = aR[t];
            v.x = to_tf32(v.x); v.y = to_tf32(v.y); v.z = to_tf32(v.z); v.w = to_tf32(v.w);
            *(float4*)&Ab[ar[t] * AS + akq[t]] = v;
        }
#pragma unroll
        for (int t = 0; t < B_F4; t++) {
            float4 v = bR[t];
            v.x = to_tf32(v.x); v.y = to_tf32(v.y); v.z = to_tf32(v.z); v.w = to_tf32(v.w);
            *(float4*)&Bb[br[t] * BNS + bc4[t]] = v;
        }
    };

    fetch(0); stage(0);
    __syncthreads();

    for (int j = 0; j < NI; j++) {
        const int buf = j & 1;
        if (j + 1 < NI) fetch(j + 1);

        const float* Ab = As + buf * A_FLOATS;
        const float* Bb = Bs + buf * B_FLOATS;
#pragma unroll
        for (int kk = 0; kk < BK; kk += 8) {
            uint32_t afr[4][4];
#pragma unroll
            for (int mt = 0; mt < 4; mt++) {
                const int m0 = warpM * 64 + mt * 16;
                afr[mt][0] = __float_as_uint(Ab[(m0 + g    ) * AS + kk + qd    ]);
                afr[mt][1] = __float_as_uint(Ab[(m0 + g + 8) * AS + kk + qd    ]);
                afr[mt][2] = __float_as_uint(Ab[(m0 + g    ) * AS + kk + qd + 4]);
                afr[mt][3] = __float_as_uint(Ab[(m0 + g + 8) * AS + kk + qd + 4]);
            }
            uint32_t bfr[NT][2];
#pragma unroll
            for (int nt = 0; nt < NT; nt++) {
                const int n0 = warpN * WN + nt * 8;
                bfr[nt][0] = __float_as_uint(Bb[(kk + qd    ) * BNS + n0 + g]);
                bfr[nt][1] = __float_as_uint(Bb[(kk + qd + 4) * BNS + n0 + g]);
            }
#pragma unroll
            for (int mt = 0; mt < 4; mt++)
#pragma unroll
                for (int nt = 0; nt < NT; nt++)
                    mma_tf32(acc[mt][nt], afr[mt][0], afr[mt][1], afr[mt][2], afr[mt][3],
                             bfr[nt][0], bfr[nt][1]);
        }

        if (j + 1 < NI) {
            stage(buf ^ 1);
            __syncthreads();
        }
    }

#pragma unroll
    for (int mt = 0; mt < 4; mt++) {
        const int row0 = rowBase + warpM * 64 + mt * 16 + g;
#pragma unroll
        for (int nt = 0; nt < NT; nt++) {
            const int c = colBase + warpN * WN + nt * 8 + qd * 2;
            const float b0 = bias[c], b1 = bias[c + 1];
            float2 v0 = make_float2(acc[mt][nt][0] + b0, acc[mt][nt][1] + b1);
            float2 v1 = make_float2(acc[mt][nt][2] + b0, acc[mt][nt][3] + b1);
            *(float2*)&C[(size_t)row0 * N + c] = v0;
            *(float2*)&C[(size_t)(row0 + 8) * N + c] = v1;
        }
    }
}

// K and V projections fused: blockIdx.z selects weight/bias/output.
// z==0 -> K, natural layout (rope reads it).
// z==1 -> V, written directly in PAIRED tile layout + tf32-rounded.
__global__ void __launch_bounds__(256)
tc_gemm_kv_kernel(const float* __restrict__ A,
                  const float* __restrict__ B0, const float* __restrict__ bias0,
                  float* __restrict__ C0,
                  const float* __restrict__ B1, const float* __restrict__ bias1,
                  float* __restrict__ C1,
                  int M, int N, int K)
{
    constexpr int BN  = 64;
    constexpr int BM  = 128;
    constexpr int BK  = 16;
    constexpr int AS  = BK + 4;
    constexpr int BNS = BN + 8;
    constexpr int A_FLOATS = BM * AS;
    constexpr int B_FLOATS = BK * BNS;
    constexpr int A_F4 = BM * BK / (4 * 256);
    constexpr int B_F4 = BK * BN / (4 * 256);
    constexpr int NT   = BN / 32;
    constexpr int WN   = BN / 4;

    const float* B    = blockIdx.z ? B1 : B0;
    const float* bias = blockIdx.z ? bias1 : bias0;
    float*       C    = blockIdx.z ? C1 : C0;

    extern __shared__ float sm[];
    float* As = sm;
    float* Bs = sm + 2 * A_FLOATS;

    const int tid   = threadIdx.x;
    const int lane  = tid & 31;
    const int w     = tid >> 5;
    const int warpM = w & 1;
    const int warpN = w >> 1;
    const int g     = lane >> 2;
    const int qd    = lane & 3;
    const int rowBase = blockIdx.y * BM;

    int ar[A_F4]; int akq[A_F4];
#pragma unroll
    for (int t = 0; t < A_F4; t++) {
        int idx = tid + t * 256;
        ar[t] = idx >> 2; akq[t] = (idx & 3) * 4;
    }
    int br[B_F4]; int bc4[B_F4];
#pragma unroll
    for (int t = 0; t < B_F4; t++) {
        int idx = tid + t * 256;
        br[t] = idx / (BN / 4); bc4[t] = (idx % (BN / 4)) * 4;
    }

    const int NI = K / BK;

    float acc[4][NT][4];
#pragma unroll
    for (int mt = 0; mt < 4; mt++)
#pragma unroll
        for (int nt = 0; nt < NT; nt++)
#pragma unroll
            for (int i = 0; i < 4; i++) acc[mt][nt][i] = 0.0f;

    float4 aR[A_F4], bR[B_F4];

    auto fetch = [&](int j) {
#pragma unroll
        for (int t = 0; t < A_F4; t++)
            aR[t] = *(const float4*)&A[(size_t)(rowBase + ar[t]) * K + j * BK + akq[t]];
#pragma unroll
        for (int t = 0; t < B_F4; t++)
            bR[t] = *(const float4*)&B[(size_t)(j * BK + br[t]) * N + bc4[t]];
    };
    auto stage = [&](int buf) {
        float* Ab = As + buf * A_FLOATS;
        float* Bb = Bs + buf * B_FLOATS;
#pragma unroll
        for (int t = 0; t < A_F4; t++) {
            float4 v = aR[t];
            v.x = to_tf32(v.x); v.y = to_tf32(v.y); v.z = to_tf32(v.z); v.w = to_tf32(v.w);
            *(float4*)&Ab[ar[t] * AS + akq[t]] = v;
        }
#pragma unroll
        for (int t = 0; t < B_F4; t++) {
            float4 v = bR[t];
            v.x = to_tf32(v.x); v.y = to_tf32(v.y); v.z = to_tf32(v.z); v.w = to_tf32(v.w);
            *(float4*)&Bb[br[t] * BNS + bc4[t]] = v;
        }
    };

    fetch(0); stage(0);
    __syncthreads();

    for (int j = 0; j < NI; j++) {
        const int buf = j & 1;
        if (j + 1 < NI) fetch(j + 1);

        const float* Ab = As + buf * A_FLOATS;
        const float* Bb = Bs + buf * B_FLOATS;
#pragma unroll
        for (int kk = 0; kk < BK; kk += 8) {
            uint32_t afr[4][4];
#pragma unroll
            for (int mt = 0; mt < 4; mt++) {
                const int m0 = warpM * 64 + mt * 16;
                afr[mt][0] = __float_as_uint(Ab[(m0 + g    ) * AS + kk + qd    ]);
                afr[mt][1] = __float_as_uint(Ab[(m0 + g + 8) * AS + kk + qd    ]);
                afr[mt][2] = __float_as_uint(Ab[(m0 + g    ) * AS + kk + qd + 4]);
                afr[mt][3] = __float_as_uint(Ab[(m0 + g + 8) * AS + kk + qd + 4]);
            }
            uint32_t bfr[NT][2];
#pragma unroll
            for (int nt = 0; nt < NT; nt++) {
                const int n0 = warpN * WN + nt * 8;
                bfr[nt][0] = __float_as_uint(Bb[(kk + qd    ) * BNS + n0 + g]);
                bfr[nt][1] = __float_as_uint(Bb[(kk + qd + 4) * BNS + n0 + g]);
            }
#pragma unroll
            for (int mt = 0; mt < 4; mt++)
#pragma unroll
                for (int nt = 0; nt < NT; nt++)
                    mma_tf32(acc[mt][nt], afr[mt][0], afr[mt][1], afr[mt][2], afr[mt][3],
                             bfr[nt][0], bfr[nt][1]);
        }

        if (j + 1 < NI) {
            stage(buf ^ 1);
            __syncthreads();
        }
    }

    if (blockIdx.z == 0) {
        // K: natural layout
#pragma unroll
        for (int mt = 0; mt < 4; mt++) {
            const int row0 = rowBase + warpM * 64 + mt * 16 + g;
#pragma unroll
            for (int nt = 0; nt < NT; nt++) {
                const int c = warpN * WN + nt * 8 + qd * 2;
                const float b0 = bias[c], b1 = bias[c + 1];
                float2 v0 = make_float2(acc[mt][nt][0] + b0, acc[mt][nt][1] + b1);
                float2 v1 = make_float2(acc[mt][nt][2] + b0, acc[mt][nt][3] + b1);
                *(float2*)&C[(size_t)row0 * N + c] = v0;
                *(float2*)&C[(size_t)(row0 + 8) * N + c] = v1;
            }
        }
    } else {
        // V: paired tile layout, tf32-rounded scalar stores
        auto wv = [&](int r, int n, float val) {
            int gt = r >> 6, rlo = r & 63;
            int p = ((rlo >> 3) << 2) | (rlo & 3);
            int comp = (rlo >> 2) & 1;
            C[(((size_t)gt * 32 + p) * 64 + n) * 2 + comp] = to_tf32(val);
        };
#pragma unroll
        for (int mt = 0; mt < 4; mt++) {
            const int row0 = rowBase + warpM * 64 + mt * 16 + g;
#pragma unroll
            for (int nt = 0; nt < NT; nt++) {
                const int c = warpN * WN + nt * 8 + qd * 2;
                const float b0 = bias[c], b1 = bias[c + 1];
                wv(row0,     c,     acc[mt][nt][0] + b0);
                wv(row0,     c + 1, acc[mt][nt][1] + b1);
                wv(row0 + 8, c,     acc[mt][nt][2] + b0);
                wv(row0 + 8, c + 1, acc[mt][nt][3] + b1);
            }
        }
    }
}

// =========================================================================
// RoPE: q in-place (natural); k read natural -> write PAIRED-TRANSPOSED
// tile layout, tf32-rounded.
// =========================================================================
__global__ void rope_kernel(float* __restrict__ q, const float* __restrict__ kin,
                            float* __restrict__ k2out)
{
    const int total = BDIM*TDIM*(NH+1)*(HD/2);
    int idx = blockIdx.x*blockDim.x + threadIdx.x;
    if (idx >= total) return;
    int pr   = idx & 31;
    int rest = idx >> 5;
    int hh   = rest % (NH+1);
    int bt   = rest / (NH+1);
    int t    = bt & (TDIM-1);

    float inv_freq = expf(-(float)pr * (9.2103403719761836f / 32.0f));
    float ang = (float)t * inv_freq;
    float sn, cs;
    sincosf(ang, &sn, &cs);

    if (hh < NH) {
        float* base = q + (size_t)bt*CDIM + hh*HD;
        float t1 = base[pr];
        float t2 = base[pr + 32];
        base[pr]      = t1*cs + t2*sn;
        base[pr + 32] = t1*sn - t2*cs;
    } else {
        const float* base = kin + (size_t)bt*HD;
        float t1 = base[pr];
        float t2 = base[pr + 32];
        float v1 = t1*cs + t2*sn;      // element d1 = pr
        float v2 = t1*sn - t2*cs;      // element d2 = pr + 32
        int gt = bt >> 6, c = bt & 63;
        int d1 = pr, d2 = pr + 32;
        int p1 = ((d1 >> 3) << 2) | (d1 & 3), c1 = (d1 >> 2) & 1;
        int p2 = ((d2 >> 3) << 2) | (d2 & 3), c2 = (d2 >> 2) & 1;
        k2out[(((size_t)gt*32 + p1)*64 + c)*2 + c1] = to_tf32(v1);
        k2out[(((size_t)gt*32 + p2)*64 + c)*2 + c2] = to_tf32(v2);
    }
}

// =========================================================================
// Tensor-core causal MQA flash attention.  BQ=BKV=64, HD=64.
// 128 threads = 4 warps; each warp owns 16 query rows.
// K/V arrive pre-paired + tf32-rounded in gmem; staging is pure cp.async
// 16B copies, double-buffered and overlapped with compute.
// =========================================================================
#define KP2S 68                  // K/V smem row stride in float2
#define QPS  68                  // QP row stride in floats
#define TILE_F2 (32*KP2S)        // 2176 float2 per tile
#define BUF_F2  (2*TILE_F2)      // K+V per buffer
#define ATT2_SMEM_BYTES (2*BUF_F2*8 + 64*QPS*4)   // 69632 + 17408 = 87040

__global__ void __launch_bounds__(128)
attn_tc_kernel(const float* __restrict__ gq, const float2* __restrict__ gk2,
               const float2* __restrict__ gv2, float* __restrict__ go)
{
    extern __shared__ float sm[];
    float*  QP  = sm + 2*BUF_F2*2;              // floats after the 2 KV buffers
    const uint32_t sbase = smem_u32(sm);

    const int qtile = (gridDim.x - 1) - blockIdx.x;   // heavy blocks first
    const int h     = blockIdx.y;
    const int b     = blockIdx.z;
    const int tid   = threadIdx.x;
    const int lane  = tid & 31;
    const int w     = tid >> 5;
    const int g     = lane >> 2;
    const int qd    = lane & 3;
    const int r0    = w * 16;
    const int qbase = qtile * 64;

    // issue cp.async for kv tile t into buffer buf (K then V), 16 chunks/thread
    auto issue_tile = [&](int t, int buf) {
        const char* kgb = (const char*)(gk2 + (size_t)(b*32 + t) * 2048);
        const char* vgb = (const char*)(gv2 + (size_t)(b*32 + t) * 2048);
        const uint32_t kb = sbase + buf * (BUF_F2 * 8);
        const uint32_t vb = kb + TILE_F2 * 8;
#pragma unroll
        for (int i = 0; i < 8; i++) {
            int idx = tid + i * 128;             // 0..1023
            int row = idx >> 5, ch = (idx & 31) << 4;
            CP_ASYNC16(kb + row * 544 + ch, kgb + row * 512 + ch);
            CP_ASYNC16(vb + row * 544 + ch, vgb + row * 512 + ch);
        }
        CP_COMMIT();
    };

    issue_tile(0, 0);   // start DMA for tile 0 immediately

    // ---- stage Q (scaled by 1/8, tf32) into QP ----
    {
        const float* qp = gq + ((size_t)(b*TDIM + qbase))*CDIM + h*HD;
#pragma unroll
        for (int i = 0; i < 8; i++) {
            int idx = tid + i*128;
            int r = idx >> 4, d4 = (idx & 15) << 2;
            float4 v = *(const float4*)(qp + (size_t)r*CDIM + d4);
            QP[r*QPS + d4+0] = to_tf32(v.x*0.125f);
            QP[r*QPS + d4+1] = to_tf32(v.y*0.125f);
            QP[r*QPS + d4+2] = to_tf32(v.z*0.125f);
            QP[r*QPS + d4+3] = to_tf32(v.w*0.125f);
        }
    }
    __syncthreads();

    // ---- Q fragments in registers (persist across kv tiles) ----
    uint32_t aQ[8][4];
#pragma unroll
    for (int kk = 0; kk < 8; kk++) {
        const int kb = kk*8;
        aQ[kk][0] = __float_as_uint(QP[(r0+g  )*QPS + kb + qd    ]);
        aQ[kk][1] = __float_as_uint(QP[(r0+g+8)*QPS + kb + qd    ]);
        aQ[kk][2] = __float_as_uint(QP[(r0+g  )*QPS + kb + qd + 4]);
        aQ[kk][3] = __float_as_uint(QP[(r0+g+8)*QPS + kb + qd + 4]);
    }

    float m_[2] = {-1e30f, -1e30f};
    float l_[2] = {0.0f, 0.0f};
    float oacc[8][4];
#pragma unroll
    for (int nt = 0; nt < 8; nt++)
#pragma unroll
        for (int i = 0; i < 4; i++) oacc[nt][i] = 0.0f;

    for (int t = 0; t <= qtile; t++) {
        const int buf = t & 1;

        CP_WAIT0();          // tile t data arrived (t+1 not yet issued)
        __syncthreads();     // all warps see tile t; all done with buf^1 from t-1

        if (t < qtile) issue_tile(t + 1, buf ^ 1);   // overlap DMA with compute

        const float2* KtP = (const float2*)sm + (size_t)buf * BUF_F2;
        const float2* VsP = KtP + TILE_F2;

        // ---- S = Q K^T ----
        float sacc[8][4];
#pragma unroll
        for (int nt = 0; nt < 8; nt++)
#pragma unroll
            for (int i = 0; i < 4; i++) sacc[nt][i] = 0.0f;

#pragma unroll
        for (int kk = 0; kk < 8; kk++) {
            float2 bf[8];
#pragma unroll
            for (int nt = 0; nt < 8; nt++)
                bf[nt] = KtP[(kk*4+qd)*KP2S + nt*8 + g];
#pragma unroll
            for (int nt = 0; nt < 8; nt++)
                mma_tf32(sacc[nt], aQ[kk][0], aQ[kk][1], aQ[kk][2], aQ[kk][3],
                         __float_as_uint(bf[nt].x), __float_as_uint(bf[nt].y));
        }

        // ---- causal mask (diagonal tile only) ----
        if (t == qtile) {
            const int ra = r0 + g, rb = ra + 8;
#pragma unroll
            for (int nt = 0; nt < 8; nt++) {
                const int ca = nt*8 + qd*2;
                if (ca     > ra) sacc[nt][0] = -1e30f;
                if (ca + 1 > ra) sacc[nt][1] = -1e30f;
                if (ca     > rb) sacc[nt][2] = -1e30f;
                if (ca + 1 > rb) sacc[nt][3] = -1e30f;
            }
        }

        // ---- online softmax ----
#pragma unroll
        for (int rr = 0; rr < 2; rr++) {
            float lm = -1e30f;
#pragma unroll
            for (int nt = 0; nt < 8; nt++)
                lm = fmaxf(lm, fmaxf(sacc[nt][2*rr], sacc[nt][2*rr+1]));
            lm = fmaxf(lm, __shfl_xor_sync(0xffffffffu, lm, 1));
            lm = fmaxf(lm, __shfl_xor_sync(0xffffffffu, lm, 2));
            float mnew  = fmaxf(m_[rr], lm);
            float alpha = __expf(m_[rr] - mnew);

            float ls = 0.0f;
#pragma unroll
            for (int nt = 0; nt < 8; nt++) {
                float p0 = __expf(sacc[nt][2*rr]   - mnew);
                float p1 = __expf(sacc[nt][2*rr+1] - mnew);
                ls += p0 + p1;
                *(float2*)&QP[(r0 + g + rr*8)*QPS + nt*8 + qd*2] =
                    make_float2(to_tf32(p0), to_tf32(p1));
            }
            ls += __shfl_xor_sync(0xffffffffu, ls, 1);
            ls += __shfl_xor_sync(0xffffffffu, ls, 2);

            m_[rr] = mnew;
            l_[rr] = l_[rr]*alpha + ls;
#pragma unroll
            for (int nt = 0; nt < 8; nt++) {
                oacc[nt][2*rr]   *= alpha;
                oacc[nt][2*rr+1] *= alpha;
            }
        }
        __syncwarp();   // P rows are warp-local

        // ---- O += P V ----
#pragma unroll
        for (int kk = 0; kk < 8; kk++) {
            const int kb = kk*8;
            uint32_t pa0 = __float_as_uint(QP[(r0+g  )*QPS + kb + qd    ]);
            uint32_t pa1 = __float_as_uint(QP[(r0+g+8)*QPS + kb + qd    ]);
            uint32_t pa2 = __float_as_uint(QP[(r0+g  )*QPS + kb + qd + 4]);
            uint32_t pa3 = __float_as_uint(QP[(r0+g+8)*QPS + kb + qd + 4]);
            float2 bv[8];
#pragma unroll
            for (int nt = 0; nt < 8; nt++)
                bv[nt] = VsP[(kk*4+qd)*KP2S + nt*8 + g];
#pragma unroll
            for (int nt = 0; nt < 8; nt++)
                mma_tf32(oacc[nt], pa0, pa1, pa2, pa3,
                         __float_as_uint(bv[nt].x), __float_as_uint(bv[nt].y));
        }
        __syncwarp();   // done reading P before next tile overwrites QP
    }

    // ---- normalize + store ----
#pragma unroll
    for (int rr = 0; rr < 2; rr++) {
        const float inv = 1.0f / l_[rr];
        float* op = go + ((size_t)(b*TDIM + qbase + r0 + g + rr*8))*CDIM + h*HD;
#pragma unroll
        for (int nt = 0; nt < 8; nt++) {
            *(float2*)&op[nt*8 + qd*2] =
                make_float2(oacc[nt][2*rr]*inv, oacc[nt][2*rr+1]*inv);
        }
    }
}

// =========================================================================
// launch
// =========================================================================
extern "C" void kernel_launch(void* const* d_in, const int* in_sizes, int n_in,
                              void* d_out, int out_size)
{
    const float* x  = (const float*)d_in[0];
    const float* Wq = (const float*)d_in[1];
    const float* bq = (const float*)d_in[2];
    const float* Wk = (const float*)d_in[3];
    const float* bk = (const float*)d_in[4];
    const float* Wv = (const float*)d_in[5];
    const float* bv = (const float*)d_in[6];
    const float* Wo = (const float*)d_in[7];
    const float* bo = (const float*)d_in[8];
    float* out = (float*)d_out;

    float *qp, *kp, *k2p, *vp, *ap;
    cudaGetSymbolAddress((void**)&qp,  g_q);
    cudaGetSymbolAddress((void**)&kp,  g_k);
    cudaGetSymbolAddress((void**)&k2p, g_k2);
    cudaGetSymbolAddress((void**)&vp,  g_v);
    cudaGetSymbolAddress((void**)&ap,  g_att);

    constexpr int SM128 = (2*(128*20) + 2*(16*136)) * 4;   // 37888 B
    constexpr int SM64  = (2*(128*20) + 2*(16*72))  * 4;   // 29696 B
    cudaFuncSetAttribute(tc_gemm_kernel<128>,
        cudaFuncAttributeMaxDynamicSharedMemorySize, SM128);
    cudaFuncSetAttribute(tc_gemm_kv_kernel,
        cudaFuncAttributeMaxDynamicSharedMemorySize, SM64);
    cudaFuncSetAttribute(attn_tc_kernel,
        cudaFuncAttributeMaxDynamicSharedMemorySize, ATT2_SMEM_BYTES);

    // Q = x @ Wq + bq   (4096 x 1024 x 1024)
    tc_gemm_kernel<128><<<dim3(CDIM/128, MROWS/128), 256, SM128>>>(
        x, Wq, bq, qp, MROWS, CDIM, CDIM);
    // K (natural), V (paired) fused in one launch
    tc_gemm_kv_kernel<<<dim3(1, MROWS/128, 2), 256, SM64>>>(
        x, Wk, bk, kp, Wv, bv, vp, MROWS, HD, CDIM);

    // RoPE: q in-place, k natural -> paired
    {
        int total = BDIM*TDIM*(NH+1)*(HD/2);
        rope_kernel<<<(total + 255)/256, 256>>>(qp, kp, k2p);
    }

    // causal MQA attention (tensor cores, cp.async double-buffered)
    attn_tc_kernel<<<dim3(TDIM/64, NH, BDIM), 128, ATT2_SMEM_BYTES>>>(
        qp, (const float2*)k2p, (const float2*)vp, ap);

    // out = att @ Wo + bo
    tc_gemm_kernel<128><<<dim3(CDIM/128, MROWS/128), 256, SM128>>>(
        ap, Wo, bo, out, MROWS, CDIM, CDIM);
}

// round 9
// speedup vs baseline: 3.3181x; 1.0180x over previous
#include <cuda_runtime.h>
#include <math.h>
#include <cstdint>

// Problem dims (fixed)
#define BDIM 2
#define TDIM 2048
#define CDIM 1024
#define NH   16
#define HD   64
#define MROWS (BDIM*TDIM)   // 4096

// ---------------- device scratch (no allocations allowed) ----------------
__device__ float g_q[(size_t)MROWS*CDIM];   // q after rope (natural layout)
__device__ float g_k[(size_t)MROWS*HD];     // k pre-rope (natural, gemm out)
__device__ float g_k2[(size_t)MROWS*HD];    // k post-rope, paired-transposed tiles
__device__ float g_v[(size_t)MROWS*HD];     // v paired tiles (gemm writes directly)
__device__ float g_att[(size_t)MROWS*CDIM]; // attn out, tf32-prerounded
__device__ float g_xr[(size_t)MROWS*CDIM];  // x  tf32-prerounded
__device__ float g_wqr[(size_t)CDIM*CDIM];  // Wq tf32-prerounded
__device__ float g_wor[(size_t)CDIM*CDIM];  // Wo tf32-prerounded

// ======================= helpers =========================================
__device__ __forceinline__ float to_tf32(float x) {
    float r; asm("cvt.rna.tf32.f32 %0, %1;" : "=f"(r) : "f"(x)); return r;
}
__device__ __forceinline__ void mma_tf32(float* c,
    uint32_t a0, uint32_t a1, uint32_t a2, uint32_t a3,
    uint32_t b0, uint32_t b1)
{
    asm volatile(
        "mma.sync.aligned.m16n8k8.row.col.f32.tf32.tf32.f32 "
        "{%0,%1,%2,%3}, {%4,%5,%6,%7}, {%8,%9}, {%0,%1,%2,%3};"
        : "+f"(c[0]), "+f"(c[1]), "+f"(c[2]), "+f"(c[3])
        : "r"(a0), "r"(a1), "r"(a2), "r"(a3), "r"(b0), "r"(b1));
}
__device__ __forceinline__ uint32_t smem_u32(const void* p) {
    uint32_t a;
    asm("{ .reg .u64 t; cvta.to.shared.u64 t, %1; cvt.u32.u64 %0, t; }"
        : "=r"(a) : "l"(p));
    return a;
}
#define CP_ASYNC16(dst_u32, src_ptr) \
    asm volatile("cp.async.cg.shared.global [%0], [%1], 16;" \
        :: "r"(dst_u32), "l"(src_ptr) : "memory")
#define CP_COMMIT() asm volatile("cp.async.commit_group;" ::: "memory")
#define CP_WAIT0()  asm volatile("cp.async.wait_group 0;"  ::: "memory")
#define CP_WAIT1()  asm volatile("cp.async.wait_group 1;"  ::: "memory")

// =========================================================================
// tf32 round-copy (RNA): out[i] = tf32(in[i]); n multiple of 4.
// =========================================================================
__global__ void round4_kernel(const float4* __restrict__ in,
                              float4* __restrict__ out, int n4)
{
    int i = blockIdx.x * blockDim.x + threadIdx.x;
    if (i >= n4) return;
    float4 v = in[i];
    v.x = to_tf32(v.x); v.y = to_tf32(v.y); v.z = to_tf32(v.z); v.w = to_tf32(v.w);
    out[i] = v;
}

// =========================================================================
// 3-stage cp.async pipelined tf32 GEMM (inputs PRE-ROUNDED to tf32):
//   C[M,N] = A[M,K] @ B[K,N] + bias[N]
// BM=128, BN=128, BK=16, 256 threads = 8 warps (2m x 4n).
// =========================================================================
#define GP_AS  20
#define GP_BNS 136
#define GP_AST (128*GP_AS)          // 2560 floats
#define GP_BST (16*GP_BNS)          // 2176 floats
#define GP_STF (GP_AST+GP_BST)      // 4736 floats per stage
#define GP_SMEM (3*GP_STF*4)        // 56832 bytes

__global__ void __launch_bounds__(256)
tc_gemm_pipe_kernel(const float* __restrict__ A, const float* __restrict__ B,
                    const float* __restrict__ bias, float* __restrict__ C,
                    int M, int N, int K)
{
    constexpr int BK = 16;
    extern __shared__ float sm[];
    const uint32_t sbase = smem_u32(sm);

    const int tid   = threadIdx.x;
    const int lane  = tid & 31;
    const int w     = tid >> 5;
    const int warpM = w & 1;
    const int warpN = w >> 1;
    const int g     = lane >> 2;
    const int qd    = lane & 3;
    const int rowBase = blockIdx.y * 128;
    const int colBase = blockIdx.x * 128;

    // 4 cp.async 16B chunks per thread per stage (A: 512 chunks, B: 512)
    const float* gsrc[4]; uint32_t soff[4]; size_t jstr[4];
#pragma unroll
    for (int i = 0; i < 4; i++) {
        int idx = tid + i * 256;
        if (idx < 512) {
            int r = idx >> 2, c4 = (idx & 3) * 4;
            gsrc[i] = A + (size_t)(rowBase + r) * K + c4;
            soff[i] = (uint32_t)(r * GP_AS + c4) * 4;
            jstr[i] = BK;
        } else {
            int e = idx - 512;
            int r = e >> 5, c4 = (e & 31) * 4;
            gsrc[i] = B + (size_t)r * N + colBase + c4;
            soff[i] = (uint32_t)(GP_AST + r * GP_BNS + c4) * 4;
            jstr[i] = (size_t)BK * N;
        }
    }
    auto issue = [&](int j, int s) {
        const uint32_t sb = sbase + (uint32_t)s * (GP_STF * 4);
#pragma unroll
        for (int i = 0; i < 4; i++)
            CP_ASYNC16(sb + soff[i], gsrc[i] + (size_t)j * jstr[i]);
        CP_COMMIT();
    };

    const int NI = K / BK;   // 64

    float acc[4][4][4];
#pragma unroll
    for (int mt = 0; mt < 4; mt++)
#pragma unroll
        for (int nt = 0; nt < 4; nt++)
#pragma unroll
            for (int i = 0; i < 4; i++) acc[mt][nt][i] = 0.0f;

    issue(0, 0);
    issue(1, 1);

    int s = 0;
    for (int j = 0; j < NI; j++) {
        CP_WAIT1();
        __syncthreads();

        if (j + 2 < NI) {
            int s2 = s + 2; if (s2 >= 3) s2 -= 3;
            issue(j + 2, s2);
        } else {
            CP_COMMIT();   // empty group keeps wait_group accounting aligned
        }

        const float* Ab = sm + s * GP_STF;
        const float* Bb = Ab + GP_AST;
#pragma unroll
        for (int kk = 0; kk < BK; kk += 8) {
            uint32_t afr[4][4];
#pragma unroll
            for (int mt = 0; mt < 4; mt++) {
                const int m0 = warpM * 64 + mt * 16;
                afr[mt][0] = __float_as_uint(Ab[(m0 + g    ) * GP_AS + kk + qd    ]);
                afr[mt][1] = __float_as_uint(Ab[(m0 + g + 8) * GP_AS + kk + qd    ]);
                afr[mt][2] = __float_as_uint(Ab[(m0 + g    ) * GP_AS + kk + qd + 4]);
                afr[mt][3] = __float_as_uint(Ab[(m0 + g + 8) * GP_AS + kk + qd + 4]);
            }
            uint32_t bfr[4][2];
#pragma unroll
            for (int nt = 0; nt < 4; nt++) {
                const int n0 = warpN * 32 + nt * 8;
                bfr[nt][0] = __float_as_uint(Bb[(kk + qd    ) * GP_BNS + n0 + g]);
                bfr[nt][1] = __float_as_uint(Bb[(kk + qd + 4) * GP_BNS + n0 + g]);
            }
#pragma unroll
            for (int mt = 0; mt < 4; mt++)
#pragma unroll
                for (int nt = 0; nt < 4; nt++)
                    mma_tf32(acc[mt][nt], afr[mt][0], afr[mt][1], afr[mt][2], afr[mt][3],
                             bfr[nt][0], bfr[nt][1]);
        }
        if (++s == 3) s = 0;
    }

#pragma unroll
    for (int mt = 0; mt < 4; mt++) {
        const int row0 = rowBase + warpM * 64 + mt * 16 + g;
#pragma unroll
        for (int nt = 0; nt < 4; nt++) {
            const int c = colBase + warpN * 32 + nt * 8 + qd * 2;
            const float b0 = bias[c], b1 = bias[c + 1];
            float2 v0 = make_float2(acc[mt][nt][0] + b0, acc[mt][nt][1] + b1);
            float2 v1 = make_float2(acc[mt][nt][2] + b0, acc[mt][nt][3] + b1);
            *(float2*)&C[(size_t)row0 * N + c] = v0;
            *(float2*)&C[(size_t)(row0 + 8) * N + c] = v1;
        }
    }
}

// =========================================================================
// K and V projections fused (unchanged from R8): z=0 -> K natural,
// z=1 -> V paired tile layout + tf32-rounded.
// =========================================================================
__global__ void __launch_bounds__(256)
tc_gemm_kv_kernel(const float* __restrict__ A,
                  const float* __restrict__ B0, const float* __restrict__ bias0,
                  float* __restrict__ C0,
                  const float* __restrict__ B1, const float* __restrict__ bias1,
                  float* __restrict__ C1,
                  int M, int N, int K)
{
    constexpr int BN  = 64;
    constexpr int BM  = 128;
    constexpr int BK  = 16;
    constexpr int AS  = BK + 4;
    constexpr int BNS = BN + 8;
    constexpr int A_FLOATS = BM * AS;
    constexpr int B_FLOATS = BK * BNS;
    constexpr int A_F4 = BM * BK / (4 * 256);
    constexpr int B_F4 = BK * BN / (4 * 256);
    constexpr int NT   = BN / 32;
    constexpr int WN   = BN / 4;

    const float* B    = blockIdx.z ? B1 : B0;
    const float* bias = blockIdx.z ? bias1 : bias0;
    float*       C    = blockIdx.z ? C1 : C0;

    extern __shared__ float sm[];
    float* As = sm;
    float* Bs = sm + 2 * A_FLOATS;

    const int tid   = threadIdx.x;
    const int lane  = tid & 31;
    const int w     = tid >> 5;
    const int warpM = w & 1;
    const int warpN = w >> 1;
    const int g     = lane >> 2;
    const int qd    = lane & 3;
    const int rowBase = blockIdx.y * BM;

    int ar[A_F4]; int akq[A_F4];
#pragma unroll
    for (int t = 0; t < A_F4; t++) {
        int idx = tid + t * 256;
        ar[t] = idx >> 2; akq[t] = (idx & 3) * 4;
    }
    int br[B_F4]; int bc4[B_F4];
#pragma unroll
    for (int t = 0; t < B_F4; t++) {
        int idx = tid + t * 256;
        br[t] = idx / (BN / 4); bc4[t] = (idx % (BN / 4)) * 4;
    }

    const int NI = K / BK;

    float acc[4][NT][4];
#pragma unroll
    for (int mt = 0; mt < 4; mt++)
#pragma unroll
        for (int nt = 0; nt < NT; nt++)
#pragma unroll
            for (int i = 0; i < 4; i++) acc[mt][nt][i] = 0.0f;

    float4 aR[A_F4], bR[B_F4];

    auto fetch = [&](int j) {
#pragma unroll
        for (int t = 0; t < A_F4; t++)
            aR[t] = *(const float4*)&A[(size_t)(rowBase + ar[t]) * K + j * BK + akq[t]];
#pragma unroll
        for (int t = 0; t < B_F4; t++)
            bR[t] = *(const float4*)&B[(size_t)(j * BK + br[t]) * N + bc4[t]];
    };
    auto stage = [&](int buf) {
        float* Ab = As + buf * A_FLOATS;
        float* Bb = Bs + buf * B_FLOATS;
#pragma unroll
        for (int t = 0; t < A_F4; t++) {
            float4 v = aR[t];
            v.x = to_tf32(v.x); v.y = to_tf32(v.y); v.z = to_tf32(v.z); v.w = to_tf32(v.w);
            *(float4*)&Ab[ar[t] * AS + akq[t]] = v;
        }
#pragma unroll
        for (int t = 0; t < B_F4; t++) {
            float4 v = bR[t];
            v.x = to_tf32(v.x); v.y = to_tf32(v.y); v.z = to_tf32(v.z); v.w = to_tf32(v.w);
            *(float4*)&Bb[br[t] * BNS + bc4[t]] = v;
        }
    };

    fetch(0); stage(0);
    __syncthreads();

    for (int j = 0; j < NI; j++) {
        const int buf = j & 1;
        if (j + 1 < NI) fetch(j + 1);

        const float* Ab = As + buf * A_FLOATS;
        const float* Bb = Bs + buf * B_FLOATS;
#pragma unroll
        for (int kk = 0; kk < BK; kk += 8) {
            uint32_t afr[4][4];
#pragma unroll
            for (int mt = 0; mt < 4; mt++) {
                const int m0 = warpM * 64 + mt * 16;
                afr[mt][0] = __float_as_uint(Ab[(m0 + g    ) * AS + kk + qd    ]);
                afr[mt][1] = __float_as_uint(Ab[(m0 + g + 8) * AS + kk + qd    ]);
                afr[mt][2] = __float_as_uint(Ab[(m0 + g    ) * AS + kk + qd + 4]);
                afr[mt][3] = __float_as_uint(Ab[(m0 + g + 8) * AS + kk + qd + 4]);
            }
            uint32_t bfr[NT][2];
#pragma unroll
            for (int nt = 0; nt < NT; nt++) {
                const int n0 = warpN * WN + nt * 8;
                bfr[nt][0] = __float_as_uint(Bb[(kk + qd    ) * BNS + n0 + g]);
                bfr[nt][1] = __float_as_uint(Bb[(kk + qd + 4) * BNS + n0 + g]);
            }
#pragma unroll
            for (int mt = 0; mt < 4; mt++)
#pragma unroll
                for (int nt = 0; nt < NT; nt++)
                    mma_tf32(acc[mt][nt], afr[mt][0], afr[mt][1], afr[mt][2], afr[mt][3],
                             bfr[nt][0], bfr[nt][1]);
        }

        if (j + 1 < NI) {
            stage(buf ^ 1);
            __syncthreads();
        }
    }

    if (blockIdx.z == 0) {
#pragma unroll
        for (int mt = 0; mt < 4; mt++) {
            const int row0 = rowBase + warpM * 64 + mt * 16 + g;
#pragma unroll
            for (int nt = 0; nt < NT; nt++) {
                const int c = warpN * WN + nt * 8 + qd * 2;
                const float b0 = bias[c], b1 = bias[c + 1];
                float2 v0 = make_float2(acc[mt][nt][0] + b0, acc[mt][nt][1] + b1);
                float2 v1 = make_float2(acc[mt][nt][2] + b0, acc[mt][nt][3] + b1);
                *(float2*)&C[(size_t)row0 * N + c] = v0;
                *(float2*)&C[(size_t)(row0 + 8) * N + c] = v1;
            }
        }
    } else {
        auto wv = [&](int r, int n, float val) {
            int gt = r >> 6, rlo = r & 63;
            int p = ((rlo >> 3) << 2) | (rlo & 3);
            int comp = (rlo >> 2) & 1;
            C[(((size_t)gt * 32 + p) * 64 + n) * 2 + comp] = to_tf32(val);
        };
#pragma unroll
        for (int mt = 0; mt < 4; mt++) {
            const int row0 = rowBase + warpM * 64 + mt * 16 + g;
#pragma unroll
            for (int nt = 0; nt < NT; nt++) {
                const int c = warpN * WN + nt * 8 + qd * 2;
                const float b0 = bias[c], b1 = bias[c + 1];
                wv(row0,     c,     acc[mt][nt][0] + b0);
                wv(row0,     c + 1, acc[mt][nt][1] + b1);
                wv(row0 + 8, c,     acc[mt][nt][2] + b0);
                wv(row0 + 8, c + 1, acc[mt][nt][3] + b1);
            }
        }
    }
}

// =========================================================================
// RoPE: q in-place (natural); k natural -> paired-transposed tiles (tf32).
// =========================================================================
__global__ void rope_kernel(float* __restrict__ q, const float* __restrict__ kin,
                            float* __restrict__ k2out)
{
    const int total = BDIM*TDIM*(NH+1)*(HD/2);
    int idx = blockIdx.x*blockDim.x + threadIdx.x;
    if (idx >= total) return;
    int pr   = idx & 31;
    int rest = idx >> 5;
    int hh   = rest % (NH+1);
    int bt   = rest / (NH+1);
    int t    = bt & (TDIM-1);

    float inv_freq = expf(-(float)pr * (9.2103403719761836f / 32.0f));
    float ang = (float)t * inv_freq;
    float sn, cs;
    sincosf(ang, &sn, &cs);

    if (hh < NH) {
        float* base = q + (size_t)bt*CDIM + hh*HD;
        float t1 = base[pr];
        float t2 = base[pr + 32];
        base[pr]      = t1*cs + t2*sn;
        base[pr + 32] = t1*sn - t2*cs;
    } else {
        const float* base = kin + (size_t)bt*HD;
        float t1 = base[pr];
        float t2 = base[pr + 32];
        float v1 = t1*cs + t2*sn;
        float v2 = t1*sn - t2*cs;
        int gt = bt >> 6, c = bt & 63;
        int d1 = pr, d2 = pr + 32;
        int p1 = ((d1 >> 3) << 2) | (d1 & 3), c1 = (d1 >> 2) & 1;
        int p2 = ((d2 >> 3) << 2) | (d2 & 3), c2 = (d2 >> 2) & 1;
        k2out[(((size_t)gt*32 + p1)*64 + c)*2 + c1] = to_tf32(v1);
        k2out[(((size_t)gt*32 + p2)*64 + c)*2 + c2] = to_tf32(v2);
    }
}

// =========================================================================
// Tensor-core causal MQA flash attention v3.  BQ=BKV=64, HD=64.
// 128 threads = 4 warps x 16 q-rows. smem = 2 KV double-buffers ONLY
// (69.6KB -> 3 CTAs/SM). Q staged through buffer1 slot, P transposed
// C-frag -> A-frag via quad shuffles (no smem P).
// =========================================================================
#define KP2S 68                  // K/V smem row stride in float2
#define TILE_F2 (32*KP2S)        // 2176 float2 per tile
#define BUF_F2  (2*TILE_F2)      // K+V per buffer
#define ATT3_SMEM_BYTES (2*BUF_F2*8)    // 69632

__global__ void __launch_bounds__(128, 3)
attn_tc_kernel(const float* __restrict__ gq, const float2* __restrict__ gk2,
               const float2* __restrict__ gv2, float* __restrict__ go)
{
    extern __shared__ float sm[];
    const uint32_t sbase = smem_u32(sm);

    const int qtile = (gridDim.x - 1) - blockIdx.x;   // heavy blocks first
    const int h     = blockIdx.y;
    const int b     = blockIdx.z;
    const int tid   = threadIdx.x;
    const int lane  = tid & 31;
    const int w     = tid >> 5;
    const int g     = lane >> 2;
    const int qd    = lane & 3;
    const int r0    = w * 16;
    const int qbase = qtile * 64;
    const unsigned FULL = 0xffffffffu;

    auto issue_tile = [&](int t, int buf) {
        const char* kgb = (const char*)(gk2 + (size_t)(b*32 + t) * 2048);
        const char* vgb = (const char*)(gv2 + (size_t)(b*32 + t) * 2048);
        const uint32_t kb = sbase + buf * (BUF_F2 * 8);
        const uint32_t vb = kb + TILE_F2 * 8;
#pragma unroll
        for (int i = 0; i < 8; i++) {
            int idx = tid + i * 128;
            int row = idx >> 5, ch = (idx & 31) << 4;
            CP_ASYNC16(kb + row * 544 + ch, kgb + row * 512 + ch);
            CP_ASYNC16(vb + row * 544 + ch, vgb + row * 512 + ch);
        }
        CP_COMMIT();
    };

    issue_tile(0, 0);   // DMA tile 0 into buffer 0

    // ---- stage Q (scaled, tf32) into buffer1's K slot (not yet in use) ----
    float* QP = sm + BUF_F2 * 2;    // float offset 8704 = start of buffer 1
#pragma unroll
    for (int i = 0; i < 8; i++) {
        int idx = tid + i*128;
        int r = idx >> 4, d4 = (idx & 15) << 2;
        const float* qp = gq + ((size_t)(b*TDIM + qbase))*CDIM + h*HD;
        float4 v = *(const float4*)(qp + (size_t)r*CDIM + d4);
        QP[r*68 + d4+0] = to_tf32(v.x*0.125f);
        QP[r*68 + d4+1] = to_tf32(v.y*0.125f);
        QP[r*68 + d4+2] = to_tf32(v.z*0.125f);
        QP[r*68 + d4+3] = to_tf32(v.w*0.125f);
    }
    __syncthreads();

    uint32_t aQ[8][4];
#pragma unroll
    for (int kk = 0; kk < 8; kk++) {
        const int kb = kk*8;
        aQ[kk][0] = __float_as_uint(QP[(r0+g  )*68 + kb + qd    ]);
        aQ[kk][1] = __float_as_uint(QP[(r0+g+8)*68 + kb + qd    ]);
        aQ[kk][2] = __float_as_uint(QP[(r0+g  )*68 + kb + qd + 4]);
        aQ[kk][3] = __float_as_uint(QP[(r0+g+8)*68 + kb + qd + 4]);
    }
    __syncthreads();   // all Q frags read before buffer1 gets tile-1 DMA

    float m_[2] = {-1e30f, -1e30f};
    float l_[2] = {0.0f, 0.0f};
    float oacc[8][4];
#pragma unroll
    for (int nt = 0; nt < 8; nt++)
#pragma unroll
        for (int i = 0; i < 4; i++) oacc[nt][i] = 0.0f;

    const int s1 = (lane & ~3) | (qd >> 1);   // P-transpose source lanes
    const int s2 = s1 + 2;
    const bool odd = qd & 1;

    for (int t = 0; t <= qtile; t++) {
        const int buf = t & 1;

        CP_WAIT0();
        __syncthreads();

        if (t < qtile) issue_tile(t + 1, buf ^ 1);

        const float2* KtP = (const float2*)sm + (size_t)buf * BUF_F2;
        const float2* VsP = KtP + TILE_F2;

        // ---- S = Q K^T ----
        float sacc[8][4];
#pragma unroll
        for (int nt = 0; nt < 8; nt++)
#pragma unroll
            for (int i = 0; i < 4; i++) sacc[nt][i] = 0.0f;

#pragma unroll
        for (int kk = 0; kk < 8; kk++) {
            float2 bf[8];
#pragma unroll
            for (int nt = 0; nt < 8; nt++)
                bf[nt] = KtP[(kk*4+qd)*KP2S + nt*8 + g];
#pragma unroll
            for (int nt = 0; nt < 8; nt++)
                mma_tf32(sacc[nt], aQ[kk][0], aQ[kk][1], aQ[kk][2], aQ[kk][3],
                         __float_as_uint(bf[nt].x), __float_as_uint(bf[nt].y));
        }

        // ---- causal mask (diagonal tile only) ----
        if (t == qtile) {
            const int ra = r0 + g, rb = ra + 8;
#pragma unroll
            for (int nt = 0; nt < 8; nt++) {
                const int ca = nt*8 + qd*2;
                if (ca     > ra) sacc[nt][0] = -1e30f;
                if (ca + 1 > ra) sacc[nt][1] = -1e30f;
                if (ca     > rb) sacc[nt][2] = -1e30f;
                if (ca + 1 > rb) sacc[nt][3] = -1e30f;
            }
        }

        // ---- online softmax; P kept in registers (tf32-rounded) ----
        float pe[8][4];   // pe[nt][rr*2+p] = P[g+8rr][nt*8+qd*2+p]
#pragma unroll
        for (int rr = 0; rr < 2; rr++) {
            float lm = -1e30f;
#pragma unroll
            for (int nt = 0; nt < 8; nt++)
                lm = fmaxf(lm, fmaxf(sacc[nt][2*rr], sacc[nt][2*rr+1]));
            lm = fmaxf(lm, __shfl_xor_sync(FULL, lm, 1));
            lm = fmaxf(lm, __shfl_xor_sync(FULL, lm, 2));
            float mnew  = fmaxf(m_[rr], lm);
            float alpha = __expf(m_[rr] - mnew);

            float ls = 0.0f;
#pragma unroll
            for (int nt = 0; nt < 8; nt++) {
                float p0 = __expf(sacc[nt][2*rr]   - mnew);
                float p1 = __expf(sacc[nt][2*rr+1] - mnew);
                ls += p0 + p1;
                pe[nt][2*rr+0] = to_tf32(p0);
                pe[nt][2*rr+1] = to_tf32(p1);
            }
            ls += __shfl_xor_sync(FULL, ls, 1);
            ls += __shfl_xor_sync(FULL, ls, 2);

            m_[rr] = mnew;
            l_[rr] = l_[rr]*alpha + ls;
#pragma unroll
            for (int nt = 0; nt < 8; nt++) {
                oacc[nt][2*rr]   *= alpha;
                oacc[nt][2*rr+1] *= alpha;
            }
        }

        // ---- O += P V  (P A-frags built via quad shuffles) ----
#pragma unroll
        for (int kk = 0; kk < 8; kk++) {
            float x0 = __shfl_sync(FULL, pe[kk][0], s1);
            float x1 = __shfl_sync(FULL, pe[kk][1], s1);
            float x2 = __shfl_sync(FULL, pe[kk][2], s1);
            float x3 = __shfl_sync(FULL, pe[kk][3], s1);
            float y0 = __shfl_sync(FULL, pe[kk][0], s2);
            float y1 = __shfl_sync(FULL, pe[kk][1], s2);
            float y2 = __shfl_sync(FULL, pe[kk][2], s2);
            float y3 = __shfl_sync(FULL, pe[kk][3], s2);
            uint32_t pa0 = __float_as_uint(odd ? x1 : x0);
            uint32_t pa1 = __float_as_uint(odd ? x3 : x2);
            uint32_t pa2 = __float_as_uint(odd ? y1 : y0);
            uint32_t pa3 = __float_as_uint(odd ? y3 : y2);

            float2 bv[8];
#pragma unroll
            for (int nt = 0; nt < 8; nt++)
                bv[nt] = VsP[(kk*4+qd)*KP2S + nt*8 + g];
#pragma unroll
            for (int nt = 0; nt < 8; nt++)
                mma_tf32(oacc[nt], pa0, pa1, pa2, pa3,
                         __float_as_uint(bv[nt].x), __float_as_uint(bv[nt].y));
        }
    }

    // ---- normalize + store (tf32-prerounded for the Wo GEMM) ----
#pragma unroll
    for (int rr = 0; rr < 2; rr++) {
        const float inv = 1.0f / l_[rr];
        float* op = go + ((size_t)(b*TDIM + qbase + r0 + g + rr*8))*CDIM + h*HD;
#pragma unroll
        for (int nt = 0; nt < 8; nt++) {
            *(float2*)&op[nt*8 + qd*2] =
                make_float2(to_tf32(oacc[nt][2*rr]*inv), to_tf32(oacc[nt][2*rr+1]*inv));
        }
    }
}

// =========================================================================
// launch
// =========================================================================
extern "C" void kernel_launch(void* const* d_in, const int* in_sizes, int n_in,
                              void* d_out, int out_size)
{
    const float* x  = (const float*)d_in[0];
    const float* Wq = (const float*)d_in[1];
    const float* bq = (const float*)d_in[2];
    const float* Wk = (const float*)d_in[3];
    const float* bk = (const float*)d_in[4];
    const float* Wv = (const float*)d_in[5];
    const float* bv = (const float*)d_in[6];
    const float* Wo = (const float*)d_in[7];
    const float* bo = (const float*)d_in[8];
    float* out = (float*)d_out;

    float *qp, *kp, *k2p, *vp, *ap, *xr, *wqr, *wor;
    cudaGetSymbolAddress((void**)&qp,  g_q);
    cudaGetSymbolAddress((void**)&kp,  g_k);
    cudaGetSymbolAddress((void**)&k2p, g_k2);
    cudaGetSymbolAddress((void**)&vp,  g_v);
    cudaGetSymbolAddress((void**)&ap,  g_att);
    cudaGetSymbolAddress((void**)&xr,  g_xr);
    cudaGetSymbolAddress((void**)&wqr, g_wqr);
    cudaGetSymbolAddress((void**)&wor, g_wor);

    constexpr int SM64 = (2*(128*20) + 2*(16*72)) * 4;   // 29696 B
    cudaFuncSetAttribute(tc_gemm_pipe_kernel,
        cudaFuncAttributeMaxDynamicSharedMemorySize, GP_SMEM);
    cudaFuncSetAttribute(tc_gemm_kv_kernel,
        cudaFuncAttributeMaxDynamicSharedMemorySize, SM64);
    cudaFuncSetAttribute(attn_tc_kernel,
        cudaFuncAttributeMaxDynamicSharedMemorySize, ATT3_SMEM_BYTES);

    // tf32 pre-round x, Wq, Wo (RNA)
    {
        int n4x = MROWS*CDIM/4, n4w = CDIM*CDIM/4;
        round4_kernel<<<(n4x + 255)/256, 256>>>((const float4*)x,  (float4*)xr,  n4x);
        round4_kernel<<<(n4w + 255)/256, 256>>>((const float4*)Wq, (float4*)wqr, n4w);
        round4_kernel<<<(n4w + 255)/256, 256>>>((const float4*)Wo, (float4*)wor, n4w);
    }

    // Q = x @ Wq + bq   (pipelined, pre-rounded inputs)
    tc_gemm_pipe_kernel<<<dim3(CDIM/128, MROWS/128), 256, GP_SMEM>>>(
        xr, wqr, bq, qp, MROWS, CDIM, CDIM);
    // K (natural), V (paired) fused
    tc_gemm_kv_kernel<<<dim3(1, MROWS/128, 2), 256, SM64>>>(
        x, Wk, bk, kp, Wv, bv, vp, MROWS, HD, CDIM);

    // RoPE: q in-place, k natural -> paired
    {
        int total = BDIM*TDIM*(NH+1)*(HD/2);
        rope_kernel<<<(total + 255)/256, 256>>>(qp, kp, k2p);
    }

    // causal MQA attention (3 CTAs/SM, reg-resident P)
    attn_tc_kernel<<<dim3(TDIM/64, NH, BDIM), 128, ATT3_SMEM_BYTES>>>(
        qp, (const float2*)k2p, (const float2*)vp, ap);

    // out = att @ Wo + bo  (pipelined; att pre-rounded by attention)
    tc_gemm_pipe_kernel<<<dim3(CDIM/128, MROWS/128), 256, GP_SMEM>>>(
        ap, wor, bo, out, MROWS, CDIM, CDIM);
}